// round 8
// baseline (speedup 1.0000x reference)
#include <cuda_runtime.h>
#include <cuda_bf16.h>
#include <cstdint>
#include <math.h>

// ---------------- problem constants ----------------
#define BATCH     32768
#define NSPARSE   26
#define NDENSE    13
#define VOCAB     10000
#define EDIM      64
#define NHEAD     2
#define DHEAD     32
#define NLAYER    3
#define H1DIM     256
#define H2DIM     128
#define DNNIN     1677
#define KPAD      1728            // 27 * 64 ; dnn input cols: [emb 0..1663 | dense 1664..1676 | pad]
#define XCOLS     39
#define ATTFLAT   (NSPARSE*EDIM)  // 1664
#define QKVR_C    256
#define MROWS     (BATCH*NSPARSE) // 851968
#define STACKW    (ATTFLAT + H2DIM)

// ---------------- scratch (device globals) ----------------
__device__ __nv_bfloat16  g_attA[(size_t)BATCH * ATTFLAT];
__device__ __nv_bfloat16  g_attB[(size_t)BATCH * ATTFLAT];
__device__ __nv_bfloat16  g_dnn_bf[(size_t)BATCH * KPAD];
__device__ __nv_bfloat16  g_h1_bf[(size_t)BATCH * H1DIM];
__device__ float          g_h2[(size_t)BATCH * H2DIM];
__device__ __nv_bfloat16  g_wqkvr_bf[NLAYER * QKVR_C * EDIM];  // [l][n=256][k=64]
__device__ __nv_bfloat16  g_w1_bf[H1DIM * KPAD];               // [n][k], k in new dnn order
__device__ __nv_bfloat16  g_w2_bf[H2DIM * H1DIM];              // [n][k]

// ---------------- mma.sync helpers ----------------
__device__ __forceinline__ uint32_t smem_u32(const void* p) {
    uint32_t a;
    asm("{ .reg .u64 t; cvta.to.shared.u64 t, %1; cvt.u32.u64 %0, t; }" : "=r"(a) : "l"(p));
    return a;
}
#define LDSM_X4(d, addr) \
    asm volatile("ldmatrix.sync.aligned.m8n8.x4.shared.b16 {%0,%1,%2,%3}, [%4];" \
        : "=r"((d)[0]), "=r"((d)[1]), "=r"((d)[2]), "=r"((d)[3]) : "r"(addr))

__device__ __forceinline__ void mma_bf16(float* c, const uint32_t* a,
                                         uint32_t b0, uint32_t b1) {
    asm volatile(
        "mma.sync.aligned.m16n8k16.row.col.f32.bf16.bf16.f32 "
        "{%0,%1,%2,%3},{%4,%5,%6,%7},{%8,%9},{%0,%1,%2,%3};"
        : "+f"(c[0]), "+f"(c[1]), "+f"(c[2]), "+f"(c[3])
        : "r"(a[0]), "r"(a[1]), "r"(a[2]), "r"(a[3]), "r"(b0), "r"(b1));
}

// ---------------- weight prep ----------------
__global__ void prep_wqkvr(const float* __restrict__ Wq, const float* __restrict__ Wk,
                           const float* __restrict__ Wv, const float* __restrict__ Wr) {
    int idx = blockIdx.x * 256 + threadIdx.x;
    if (idx >= NLAYER * QKVR_C * EDIM) return;
    int l = idx >> 14, rem = idx & 16383;
    int n = rem >> 6, k = rem & 63;
    const float* Ws[4] = {Wq, Wk, Wv, Wr};
    float v = Ws[n >> 6][(l * EDIM + k) * EDIM + (n & 63)];
    g_wqkvr_bf[idx] = __float2bfloat16_rn(v);
}
// W1 rows permuted: dnn col k<1664 -> old row 13+k (emb); 1664<=k<1677 -> old k-1664 (dense)
__global__ void prep_w1(const float* __restrict__ W1) {
    int idx = blockIdx.x * 256 + threadIdx.x;
    if (idx >= H1DIM * KPAD) return;
    int n = idx / KPAD, k = idx % KPAD;
    float v = 0.f;
    if (k < ATTFLAT)            v = W1[(long)(13 + k) * H1DIM + n];
    else if (k < ATTFLAT + NDENSE) v = W1[(long)(k - ATTFLAT) * H1DIM + n];
    g_w1_bf[idx] = __float2bfloat16_rn(v);
}
__global__ void prep_w2(const float* __restrict__ W2) {
    int idx = blockIdx.x * 256 + threadIdx.x;
    if (idx >= H2DIM * H1DIM) return;
    int n = idx / H1DIM, k = idx % H1DIM;
    g_w2_bf[idx] = __float2bfloat16_rn(W2[(long)k * H2DIM + n]);
}

// ---------------- embedding gather: warp per (b, f) row ----------------
__global__ __launch_bounds__(256)
void gather_emb(const int* __restrict__ sidx, const float* __restrict__ emb) {
    int row = blockIdx.x * 8 + (threadIdx.x >> 5);   // b*26 + f
    int lane = threadIdx.x & 31;
    int b = row / NSPARSE, f = row % NSPARSE;
    int vrow = sidx[(long)b * NSPARSE + f];
    const float2 e2 = *(const float2*)(emb + ((long)f * VOCAB + vrow) * EDIM + 2 * lane);
    __nv_bfloat162 h = __floats2bfloat162_rn(e2.x, e2.y);
    *(__nv_bfloat162*)(g_dnn_bf + (long)b * KPAD + f * EDIM + 2 * lane) = h;
}
// dense + pad columns of dnn input
__global__ __launch_bounds__(256)
void dense_pad(const float* __restrict__ X) {
    long idx = (long)blockIdx.x * 256 + threadIdx.x;   // B*64
    int b = (int)(idx >> 6), cc = (int)(idx & 63);
    float v = (cc < NDENSE) ? X[(long)b * XCOLS + NSPARSE + cc] : 0.f;
    g_dnn_bf[(long)b * KPAD + ATTFLAT + cc] = __float2bfloat16_rn(v);
}

// ---------------- fused proj + attention layer ----------------
// CTA = 128 threads, 4 samples. Warp w computes qkvr cols [w*64, w*64+64) via mma,
// then runs attention for 2 (sample, head) tasks out of smem.
#define F_SPB   4
#define SQROWB  528   // bytes per sQ row (264 bf16)
#define OFF_W   0
#define OFF_A   32768
#define OFF_Q   47104
#define F_SMEM  (OFF_Q + 112 * SQROWB)   // 106240

__global__ __launch_bounds__(128)
void fused_layer(const __nv_bfloat16* __restrict__ Ain, long sstride,
                 const __nv_bfloat16* __restrict__ W,
                 __nv_bfloat16* __restrict__ Aout) {
    extern __shared__ __align__(1024) unsigned char sm[];
    const int tid = threadIdx.x, wid = tid >> 5, lane = tid & 31;
    const long b0 = (long)blockIdx.x * F_SPB;

    // load W tile: 256 rows x 128 B, swizzled
    const unsigned char* Wg = (const unsigned char*)W;
#pragma unroll 4
    for (int u = tid; u < 2048; u += 128) {
        int r = u >> 3, ck = u & 7;
        *(uint4*)(sm + OFF_W + r * 128 + ((ck ^ (r & 7)) << 4)) =
            *(const uint4*)(Wg + (long)r * 128 + ck * 16);
    }
    // load A: 104 rows (4 samples x 26 features) x 128 B; rows 104..111 zero
#pragma unroll
    for (int u = tid; u < 896; u += 128) {
        int r = u >> 3, ck = u & 7;
        uint4 v = make_uint4(0u, 0u, 0u, 0u);
        if (r < 104) {
            int s = r / 26, f = r - s * 26;
            v = *(const uint4*)((const unsigned char*)(Ain + (b0 + s) * sstride + f * EDIM) + ck * 16);
        }
        *(uint4*)(sm + OFF_A + r * 128 + ((ck ^ (r & 7)) << 4)) = v;
    }
    __syncthreads();

    const uint32_t sA = smem_u32(sm + OFF_A);
    const uint32_t sW = smem_u32(sm + OFF_W);
    const int sel = lane >> 3, rr = lane & 7;
    const int ar = (sel & 1) * 8 + rr, ahi = sel >> 1;
    const int br = wid * 64 + (sel >> 1) * 8 + rr, bhi = sel & 1;
    const int g = lane >> 2, t4 = lane & 3;

    // mma: 7 m-tiles of 16 rows; warp covers its 64 n-cols
    for (int mt = 0; mt < 7; mt++) {
        float acc[8][4];
#pragma unroll
        for (int ni = 0; ni < 8; ni++)
#pragma unroll
            for (int q = 0; q < 4; q++) acc[ni][q] = 0.f;
#pragma unroll
        for (int kk = 0; kk < 4; kk++) {
            uint32_t a[4];
            int r = mt * 16 + ar;
            LDSM_X4(a, sA + r * 128 + ((uint32_t)((2 * kk + ahi) ^ (r & 7)) << 4));
#pragma unroll
            for (int nip = 0; nip < 4; nip++) {
                int rb = br + nip * 16;
                uint32_t b[4];
                LDSM_X4(b, sW + rb * 128 + ((uint32_t)((2 * kk + bhi) ^ (rb & 7)) << 4));
                mma_bf16(acc[nip * 2],     a, b[0], b[1]);
                mma_bf16(acc[nip * 2 + 1], a, b[2], b[3]);
            }
        }
#pragma unroll
        for (int ni = 0; ni < 8; ni++) {
            int col = wid * 64 + ni * 8 + 2 * t4;
            int r0 = mt * 16 + g;
            *(__nv_bfloat162*)(sm + OFF_Q + (long)r0 * SQROWB + col * 2) =
                __floats2bfloat162_rn(acc[ni][0], acc[ni][1]);
            *(__nv_bfloat162*)(sm + OFF_Q + (long)(r0 + 8) * SQROWB + col * 2) =
                __floats2bfloat162_rn(acc[ni][2], acc[ni][3]);
        }
    }
    __syncthreads();

    // attention: warp handles tasks (s = wid, h = 0/1); p buffer overlays W region
    float* pwarp = (float*)(sm + wid * 3328);
#pragma unroll
    for (int tt = 0; tt < 2; tt++) {
        const int s = wid, h = tt;
        const unsigned char* Q = sm + OFF_Q + (long)s * 26 * SQROWB;

        float kreg[32];
        if (lane < NSPARSE) {
            const unsigned char* kp = Q + lane * SQROWB + (EDIM + h * DHEAD) * 2;
#pragma unroll
            for (int c = 0; c < 4; c++) {
                uint4 u = *(const uint4*)(kp + c * 16);
                const __nv_bfloat162* hb = (const __nv_bfloat162*)&u;
#pragma unroll
                for (int q = 0; q < 4; q++) {
                    float2 f2 = __bfloat1622float2(hb[q]);
                    kreg[c * 8 + 2 * q] = f2.x; kreg[c * 8 + 2 * q + 1] = f2.y;
                }
            }
        } else {
#pragma unroll
            for (int d = 0; d < 32; d++) kreg[d] = 0.f;
        }

        float sc[NSPARSE];
#pragma unroll
        for (int i = 0; i < NSPARSE; i++) {
            const unsigned char* qp = Q + i * SQROWB + (h * DHEAD) * 2;
            float acc = 0.f;
#pragma unroll
            for (int c = 0; c < 4; c++) {
                uint4 u = *(const uint4*)(qp + c * 16);
                const __nv_bfloat162* hb = (const __nv_bfloat162*)&u;
#pragma unroll
                for (int q = 0; q < 4; q++) {
                    float2 f2 = __bfloat1622float2(hb[q]);
                    acc += f2.x * kreg[c * 8 + 2 * q] + f2.y * kreg[c * 8 + 2 * q + 1];
                }
            }
            sc[i] = (lane < NSPARSE) ? acc : -INFINITY;
        }
#pragma unroll
        for (int i = 0; i < NSPARSE; i++) {
            float m = sc[i];
#pragma unroll
            for (int o = 16; o > 0; o >>= 1) m = fmaxf(m, __shfl_xor_sync(0xffffffffu, m, o));
            float e = expf(sc[i] - m);
            float ssum = e;
#pragma unroll
            for (int o = 16; o > 0; o >>= 1) ssum += __shfl_xor_sync(0xffffffffu, ssum, o);
            pwarp[i * 32 + lane] = e / ssum;
        }
        __syncwarp();

        float vreg[NSPARSE];
#pragma unroll
        for (int j = 0; j < NSPARSE; j++)
            vreg[j] = __bfloat162float(*(const __nv_bfloat16*)
                        (Q + j * SQROWB + (2 * EDIM + h * DHEAD + lane) * 2));

        __nv_bfloat16* dst = Aout + (b0 + s) * ATTFLAT + h * DHEAD + lane;
#pragma unroll
        for (int i = 0; i < NSPARSE; i++) {
            float acc = __bfloat162float(*(const __nv_bfloat16*)
                          (Q + i * SQROWB + (3 * EDIM + h * DHEAD + lane) * 2));
            const float* pr = &pwarp[i * 32];
#pragma unroll
            for (int j = 0; j < 24; j += 4) {
                float4 p4 = *(const float4*)&pr[j];
                acc += p4.x * vreg[j] + p4.y * vreg[j + 1]
                     + p4.z * vreg[j + 2] + p4.w * vreg[j + 3];
            }
            acc += pr[24] * vreg[24] + pr[25] * vreg[25];
            dst[(size_t)i * EDIM] = __float2bfloat16_rn(fmaxf(acc, 0.f));
        }
        __syncwarp();
    }
}

// ---------------- bf16 mma.sync GEMM (dnn layers) ----------------
template<int KTOT, int NTFULL, bool RELU, bool BF16OUT>
__global__ __launch_bounds__(256)
void gemm_mma(const __nv_bfloat16* __restrict__ A,
              const __nv_bfloat16* __restrict__ Bop,
              const float* __restrict__ bias,
              void* __restrict__ Cout) {
    __shared__ __align__(1024) unsigned char smA[128 * 128];
    __shared__ __align__(1024) unsigned char smB[128 * 128];
    const int tid = threadIdx.x;
    const int wid = tid >> 5, lane = tid & 31;
    const int wm = wid & 3, wn = wid >> 2;
    const long m0 = (long)blockIdx.x * 128;
    const int n0 = blockIdx.y * 128;

    float acc[2][8][4];
#pragma unroll
    for (int mi = 0; mi < 2; mi++)
#pragma unroll
        for (int ni = 0; ni < 8; ni++)
#pragma unroll
            for (int q = 0; q < 4; q++) acc[mi][ni][q] = 0.f;

    const uint32_t sA = smem_u32(smA), sB = smem_u32(smB);
    const int sel = lane >> 3, rr = lane & 7;
    const int arow0 = wm * 32 + (sel & 1) * 8 + rr;
    const int ahi = sel >> 1;
    const int brow0 = wn * 64 + (sel >> 1) * 8 + rr;
    const int bhi = sel & 1;

    const int NCH = KTOT / 64;
    for (int ch = 0; ch < NCH; ch++) {
        const unsigned char* Ag = (const unsigned char*)A + (m0 * KTOT + (long)ch * 64) * 2;
        const unsigned char* Bg = (const unsigned char*)Bop + (((long)n0 * KTOT) + (long)ch * 64) * 2;
#pragma unroll 2
        for (int u = tid; u < 1024; u += 256) {
            int r = u >> 3, ck = u & 7;
            uint32_t so = (uint32_t)(r * 128 + ((ck ^ (r & 7)) << 4));
            *(uint4*)(smA + so) = *(const uint4*)(Ag + (long)r * (KTOT * 2) + ck * 16);
            *(uint4*)(smB + so) = *(const uint4*)(Bg + (long)r * (KTOT * 2) + ck * 16);
        }
        __syncthreads();
#pragma unroll
        for (int kk = 0; kk < 4; kk++) {
            uint32_t a[2][4];
#pragma unroll
            for (int mi = 0; mi < 2; mi++) {
                int r = arow0 + mi * 16;
                uint32_t addr = sA + r * 128 + ((uint32_t)((2 * kk + ahi) ^ (r & 7)) << 4);
                LDSM_X4(a[mi], addr);
            }
#pragma unroll
            for (int nip = 0; nip < 4; nip++) {
                int r = brow0 + nip * 16;
                uint32_t addr = sB + r * 128 + ((uint32_t)((2 * kk + bhi) ^ (r & 7)) << 4);
                uint32_t b[4];
                LDSM_X4(b, addr);
#pragma unroll
                for (int mi = 0; mi < 2; mi++) {
                    mma_bf16(acc[mi][nip * 2],     a[mi], b[0], b[1]);
                    mma_bf16(acc[mi][nip * 2 + 1], a[mi], b[2], b[3]);
                }
            }
        }
        __syncthreads();
    }

    const int g = lane >> 2, t = lane & 3;
#pragma unroll
    for (int mi = 0; mi < 2; mi++) {
#pragma unroll
        for (int ni = 0; ni < 8; ni++) {
            int col = n0 + wn * 64 + ni * 8 + 2 * t;
            long r0 = m0 + wm * 32 + mi * 16 + g;
            float c0 = acc[mi][ni][0], c1 = acc[mi][ni][1];
            float c2 = acc[mi][ni][2], c3 = acc[mi][ni][3];
            if (bias != nullptr) {
                float bb0 = bias[col], bb1 = bias[col + 1];
                c0 += bb0; c1 += bb1; c2 += bb0; c3 += bb1;
            }
            if (RELU) {
                c0 = fmaxf(c0, 0.f); c1 = fmaxf(c1, 0.f);
                c2 = fmaxf(c2, 0.f); c3 = fmaxf(c3, 0.f);
            }
            if (BF16OUT) {
                __nv_bfloat16* base = (__nv_bfloat16*)Cout;
                *(__nv_bfloat162*)(base + r0 * NTFULL + col)       = __floats2bfloat162_rn(c0, c1);
                *(__nv_bfloat162*)(base + (r0 + 8) * NTFULL + col) = __floats2bfloat162_rn(c2, c3);
            } else {
                float* base = (float*)Cout;
                *(float2*)(base + r0 * NTFULL + col)       = make_float2(c0, c1);
                *(float2*)(base + (r0 + 8) * NTFULL + col) = make_float2(c2, c3);
            }
        }
    }
}

// ---------------- head: per-sample dots + sigmoid (bf16 att) ----------------
__global__ __launch_bounds__(256)
void head_kernel(const float* __restrict__ X,
                 const __nv_bfloat16* __restrict__ att,
                 const float* __restrict__ outW,
                 const float* __restrict__ linW, const float* __restrict__ linb,
                 float* __restrict__ out) {
    __shared__ __align__(16) float soW[STACKW];
    int tid = threadIdx.x;
    for (int i = tid; i < STACKW; i += 256) soW[i] = outW[i];
    __syncthreads();
    int warp = tid >> 5, lane = tid & 31;
    int s = blockIdx.x * 8 + warp;
    const uint4* ap = (const uint4*)(att + (size_t)s * ATTFLAT);   // 208 uint4 of 8 bf16
    float acc = 0.f;
#pragma unroll
    for (int t = 0; t < 7; t++) {
        int i = t * 32 + lane;
        if (t < 6 || lane < 16) {
            uint4 u = ap[i];
            const __nv_bfloat162* hb = (const __nv_bfloat162*)&u;
            const float* w = &soW[i * 8];
#pragma unroll
            for (int q = 0; q < 4; q++) {
                float2 f2 = __bfloat1622float2(hb[q]);
                acc += f2.x * w[2 * q] + f2.y * w[2 * q + 1];
            }
        }
    }
    {
        const float4* hp = (const float4*)&g_h2[(size_t)s * H2DIM];
        float4 a = hp[lane];
        const float4* ow4 = (const float4*)soW;
        float4 w = ow4[ATTFLAT / 4 + lane];
        acc += a.x * w.x + a.y * w.y + a.z * w.z + a.w * w.w;
    }
    float al = X[(size_t)s * XCOLS + lane] * linW[lane];
    if (lane < XCOLS - 32) al += X[(size_t)s * XCOLS + 32 + lane] * linW[32 + lane];
#pragma unroll
    for (int o = 16; o > 0; o >>= 1) {
        acc += __shfl_xor_sync(0xffffffffu, acc, o);
        al  += __shfl_xor_sync(0xffffffffu, al, o);
    }
    if (lane == 0) {
        float lin = fmaxf(al + linb[0], 0.f);
        out[s] = 1.f / (1.f + expf(-(lin + acc)));
    }
}

// ---------------- launcher ----------------
extern "C" void kernel_launch(void* const* d_in, const int* in_sizes, int n_in,
                              void* d_out, int out_size) {
    (void)in_sizes; (void)n_in; (void)out_size;
    const float* X    = (const float*)d_in[0];
    const int*   sidx = (const int*)  d_in[1];
    const float* emb  = (const float*)d_in[2];
    const float* Wq   = (const float*)d_in[3];
    const float* Wk   = (const float*)d_in[4];
    const float* Wv   = (const float*)d_in[5];
    const float* Wr   = (const float*)d_in[6];
    const float* W1   = (const float*)d_in[7];
    const float* b1   = (const float*)d_in[8];
    const float* W2   = (const float*)d_in[9];
    const float* b2   = (const float*)d_in[10];
    const float* outW = (const float*)d_in[11];
    const float* linW = (const float*)d_in[12];
    const float* linb = (const float*)d_in[13];
    float* out = (float*)d_out;

    void *pAttA, *pAttB, *pDnn, *pH1, *pH2, *pWqkvr, *pW1b, *pW2b;
    cudaGetSymbolAddress(&pAttA,  g_attA);
    cudaGetSymbolAddress(&pAttB,  g_attB);
    cudaGetSymbolAddress(&pDnn,   g_dnn_bf);
    cudaGetSymbolAddress(&pH1,    g_h1_bf);
    cudaGetSymbolAddress(&pH2,    g_h2);
    cudaGetSymbolAddress(&pWqkvr, g_wqkvr_bf);
    cudaGetSymbolAddress(&pW1b,   g_w1_bf);
    cudaGetSymbolAddress(&pW2b,   g_w2_bf);

    cudaFuncSetAttribute((const void*)fused_layer,
                         cudaFuncAttributeMaxDynamicSharedMemorySize, F_SMEM);

    prep_wqkvr<<<(NLAYER * QKVR_C * EDIM + 255) / 256, 256>>>(Wq, Wk, Wv, Wr);
    prep_w1<<<(H1DIM * KPAD + 255) / 256, 256>>>(W1);
    prep_w2<<<(H2DIM * H1DIM + 255) / 256, 256>>>(W2);
    gather_emb<<<MROWS / 8, 256>>>(sidx, emb);
    dense_pad<<<BATCH * 64 / 256, 256>>>(X);

    const __nv_bfloat16* wbase = (const __nv_bfloat16*)pWqkvr;
    // layer 1: emb (inside dnn buffer, stride KPAD) -> attA
    fused_layer<<<BATCH / F_SPB, 128, F_SMEM>>>(
        (const __nv_bfloat16*)pDnn, (long)KPAD, wbase, (__nv_bfloat16*)pAttA);
    // layer 2: attA -> attB
    fused_layer<<<BATCH / F_SPB, 128, F_SMEM>>>(
        (const __nv_bfloat16*)pAttA, (long)ATTFLAT, wbase + (size_t)QKVR_C * EDIM,
        (__nv_bfloat16*)pAttB);
    // layer 3: attB -> attA
    fused_layer<<<BATCH / F_SPB, 128, F_SMEM>>>(
        (const __nv_bfloat16*)pAttB, (long)ATTFLAT, wbase + (size_t)2 * QKVR_C * EDIM,
        (__nv_bfloat16*)pAttA);

    gemm_mma<KPAD, H1DIM, true, true><<<dim3(BATCH / 128, H1DIM / 128), 256>>>(
        (const __nv_bfloat16*)pDnn, (const __nv_bfloat16*)pW1b, b1, pH1);
    gemm_mma<H1DIM, H2DIM, true, false><<<dim3(BATCH / 128, 1), 256>>>(
        (const __nv_bfloat16*)pH1, (const __nv_bfloat16*)pW2b, b2, pH2);
    head_kernel<<<BATCH / 8, 256>>>(X, (const __nv_bfloat16*)pAttA, outW, linW, linb, out);
}

// round 9
// speedup vs baseline: 1.8444x; 1.8444x over previous
#include <cuda_runtime.h>
#include <cuda_bf16.h>
#include <cstdint>
#include <math.h>

// ---------------- problem constants ----------------
#define BATCH     32768
#define NSPARSE   26
#define NDENSE    13
#define VOCAB     10000
#define EDIM      64
#define NHEAD     2
#define DHEAD     32
#define NLAYER    3
#define H1DIM     256
#define H2DIM     128
#define DNNIN     1677
#define KPAD      1728            // 27*64 ; dnn cols: [emb 0..1663 | dense | pad]
#define XCOLS     39
#define ATTFLAT   (NSPARSE*EDIM)  // 1664
#define QKVR_C    256
#define MROWS     (BATCH*NSPARSE)
#define STACKW    (ATTFLAT + H2DIM)

// ---------------- scratch ----------------
__device__ __nv_bfloat16  g_attA[(size_t)BATCH * ATTFLAT];
__device__ __nv_bfloat16  g_attB[(size_t)BATCH * ATTFLAT];
__device__ __nv_bfloat16  g_dnn_bf[(size_t)BATCH * KPAD];
__device__ __nv_bfloat16  g_h1_bf[(size_t)BATCH * H1DIM];
__device__ float          g_h2[(size_t)BATCH * H2DIM];
__device__ __nv_bfloat16  g_wqkvr_bf[NLAYER * QKVR_C * EDIM];  // [l][n][k]
__device__ __nv_bfloat16  g_w1_bf[H1DIM * KPAD];
__device__ __nv_bfloat16  g_w2_bf[H2DIM * H1DIM];

// ---------------- mma.sync helpers ----------------
__device__ __forceinline__ uint32_t smem_u32(const void* p) {
    uint32_t a;
    asm("{ .reg .u64 t; cvta.to.shared.u64 t, %1; cvt.u32.u64 %0, t; }" : "=r"(a) : "l"(p));
    return a;
}
#define LDSM_X4(d, addr) \
    asm volatile("ldmatrix.sync.aligned.m8n8.x4.shared.b16 {%0,%1,%2,%3}, [%4];" \
        : "=r"((d)[0]), "=r"((d)[1]), "=r"((d)[2]), "=r"((d)[3]) : "r"(addr))

__device__ __forceinline__ void mma_bf16(float* c, const uint32_t* a,
                                         uint32_t b0, uint32_t b1) {
    asm volatile(
        "mma.sync.aligned.m16n8k16.row.col.f32.bf16.bf16.f32 "
        "{%0,%1,%2,%3},{%4,%5,%6,%7},{%8,%9},{%0,%1,%2,%3};"
        : "+f"(c[0]), "+f"(c[1]), "+f"(c[2]), "+f"(c[3])
        : "r"(a[0]), "r"(a[1]), "r"(a[2]), "r"(a[3]), "r"(b0), "r"(b1));
}

// ---------------- weight prep ----------------
__global__ void prep_wqkvr(const float* __restrict__ Wq, const float* __restrict__ Wk,
                           const float* __restrict__ Wv, const float* __restrict__ Wr) {
    int idx = blockIdx.x * 256 + threadIdx.x;
    if (idx >= NLAYER * QKVR_C * EDIM) return;
    int l = idx >> 14, rem = idx & 16383;
    int n = rem >> 6, k = rem & 63;
    const float* Ws[4] = {Wq, Wk, Wv, Wr};
    float v = Ws[n >> 6][(l * EDIM + k) * EDIM + (n & 63)];
    g_wqkvr_bf[idx] = __float2bfloat16_rn(v);
}
__global__ void prep_w1(const float* __restrict__ W1) {
    int idx = blockIdx.x * 256 + threadIdx.x;
    if (idx >= H1DIM * KPAD) return;
    int n = idx / KPAD, k = idx % KPAD;
    float v = 0.f;
    if (k < ATTFLAT)               v = W1[(long)(13 + k) * H1DIM + n];
    else if (k < ATTFLAT + NDENSE) v = W1[(long)(k - ATTFLAT) * H1DIM + n];
    g_w1_bf[idx] = __float2bfloat16_rn(v);
}
__global__ void prep_w2(const float* __restrict__ W2) {
    int idx = blockIdx.x * 256 + threadIdx.x;
    if (idx >= H2DIM * H1DIM) return;
    int n = idx / H1DIM, k = idx % H1DIM;
    g_w2_bf[idx] = __float2bfloat16_rn(W2[(long)k * H2DIM + n]);
}

// ---------------- embedding gather ----------------
__global__ __launch_bounds__(256)
void gather_emb(const int* __restrict__ sidx, const float* __restrict__ emb) {
    int row = blockIdx.x * 8 + (threadIdx.x >> 5);
    int lane = threadIdx.x & 31;
    int b = row / NSPARSE, f = row % NSPARSE;
    int vrow = sidx[(long)b * NSPARSE + f];
    const float2 e2 = *(const float2*)(emb + ((long)f * VOCAB + vrow) * EDIM + 2 * lane);
    *(__nv_bfloat162*)(g_dnn_bf + (long)b * KPAD + f * EDIM + 2 * lane) =
        __floats2bfloat162_rn(e2.x, e2.y);
}
__global__ __launch_bounds__(256)
void dense_pad(const float* __restrict__ X) {
    long idx = (long)blockIdx.x * 256 + threadIdx.x;
    int b = (int)(idx >> 6), cc = (int)(idx & 63);
    float v = (cc < NDENSE) ? X[(long)b * XCOLS + NSPARSE + cc] : 0.f;
    g_dnn_bf[(long)b * KPAD + ATTFLAT + cc] = __float2bfloat16_rn(v);
}

// ---------------- fused proj + attention layer ----------------
// 256 threads, 8 samples/CTA (208 A-rows = 13 m16 tiles). Warp w owns qkvr
// cols [32w, 32w+32): B frags register-cached, then attention for (s=w, h=0/1).
#define F_SPB   8
#define SQROWB  528
#define OFF_W   0
#define OFF_A   32768
#define OFF_Q   (OFF_A + 208 * 128)            // 59392
#define F_SMEM  (OFF_Q + 208 * SQROWB)         // 169216

__global__ __launch_bounds__(256, 1)
void fused_layer(const __nv_bfloat16* __restrict__ Ain, long sstride,
                 const __nv_bfloat16* __restrict__ W,
                 __nv_bfloat16* __restrict__ Aout) {
    extern __shared__ __align__(1024) unsigned char sm[];
    const int tid = threadIdx.x, wid = tid >> 5, lane = tid & 31;
    const long b0 = (long)blockIdx.x * F_SPB;

    // W tile: 256 rows x 128 B, swizzled
    const unsigned char* Wg = (const unsigned char*)W;
#pragma unroll 4
    for (int u = tid; u < 2048; u += 256) {
        int r = u >> 3, ck = u & 7;
        *(uint4*)(sm + OFF_W + r * 128 + ((ck ^ (r & 7)) << 4)) =
            *(const uint4*)(Wg + (long)r * 128 + ck * 16);
    }
    // A tile: 208 rows x 128 B, swizzled
#pragma unroll 4
    for (int u = tid; u < 1664; u += 256) {
        int r = u >> 3, ck = u & 7;
        int s = r / 26, f = r - s * 26;
        uint4 v = *(const uint4*)((const unsigned char*)(Ain + (b0 + s) * sstride + f * EDIM) + ck * 16);
        *(uint4*)(sm + OFF_A + r * 128 + ((ck ^ (r & 7)) << 4)) = v;
    }
    __syncthreads();

    const uint32_t sA = smem_u32(sm + OFF_A);
    const uint32_t sW = smem_u32(sm + OFF_W);
    const int sel = lane >> 3, rr = lane & 7;
    const int g = lane >> 2, t4 = lane & 3;

    // cache B fragments for this warp's 32 cols: 4 k-steps x 2 n16 tiles
    uint32_t bfr[4][2][4];
#pragma unroll
    for (int kk = 0; kk < 4; kk++)
#pragma unroll
        for (int nip = 0; nip < 2; nip++) {
            int rb = wid * 32 + nip * 16 + (sel >> 1) * 8 + rr;
            LDSM_X4(bfr[kk][nip],
                    sW + rb * 128 + ((uint32_t)((2 * kk + (sel & 1)) ^ (rb & 7)) << 4));
        }

    // 13 m-tiles of 16 rows
    for (int mt = 0; mt < 13; mt++) {
        float acc[4][4];
#pragma unroll
        for (int ni = 0; ni < 4; ni++)
#pragma unroll
            for (int q = 0; q < 4; q++) acc[ni][q] = 0.f;
#pragma unroll
        for (int kk = 0; kk < 4; kk++) {
            uint32_t a[4];
            int ra = mt * 16 + (sel & 1) * 8 + rr;
            LDSM_X4(a, sA + ra * 128 + ((uint32_t)((2 * kk + (sel >> 1)) ^ (ra & 7)) << 4));
#pragma unroll
            for (int nip = 0; nip < 2; nip++) {
                mma_bf16(acc[nip * 2],     a, bfr[kk][nip][0], bfr[kk][nip][1]);
                mma_bf16(acc[nip * 2 + 1], a, bfr[kk][nip][2], bfr[kk][nip][3]);
            }
        }
#pragma unroll
        for (int ni = 0; ni < 4; ni++) {
            int col = wid * 32 + ni * 8 + 2 * t4;
            int r0 = mt * 16 + g;
            *(__nv_bfloat162*)(sm + OFF_Q + (long)r0 * SQROWB + col * 2) =
                __floats2bfloat162_rn(acc[ni][0], acc[ni][1]);
            *(__nv_bfloat162*)(sm + OFF_Q + (long)(r0 + 8) * SQROWB + col * 2) =
                __floats2bfloat162_rn(acc[ni][2], acc[ni][3]);
        }
    }
    __syncthreads();

    // attention: warp w -> sample s = w, heads 0 and 1. p-buffer overlays W.
    const int s = wid;
    const unsigned char* Qs = sm + OFF_Q + (long)s * 26 * SQROWB;
    float* pbuf = (float*)(sm + wid * 2944);
    const bool rowv = (lane < NSPARSE);

#pragma unroll
    for (int h = 0; h < 2; h++) {
        // phase 1: lane i owns score row i
        float q[32];
        if (rowv) {
#pragma unroll
            for (int c = 0; c < 8; c++) {
                uint2 u = *(const uint2*)(Qs + lane * SQROWB + h * 64 + c * 8);
                const __nv_bfloat162* hb = (const __nv_bfloat162*)&u;
                float2 f0 = __bfloat1622float2(hb[0]);
                float2 f1 = __bfloat1622float2(hb[1]);
                q[c * 4] = f0.x; q[c * 4 + 1] = f0.y; q[c * 4 + 2] = f1.x; q[c * 4 + 3] = f1.y;
            }
        } else {
#pragma unroll
            for (int d = 0; d < 32; d++) q[d] = 0.f;
        }
        float scr[26];
#pragma unroll
        for (int j = 0; j < 26; j++) {
            float acc = 0.f;
#pragma unroll
            for (int c = 0; c < 8; c++) {
                uint2 u = *(const uint2*)(Qs + j * SQROWB + 128 + h * 64 + c * 8);  // broadcast
                const __nv_bfloat162* hb = (const __nv_bfloat162*)&u;
                float2 f0 = __bfloat1622float2(hb[0]);
                float2 f1 = __bfloat1622float2(hb[1]);
                acc += f0.x * q[c * 4] + f0.y * q[c * 4 + 1]
                     + f1.x * q[c * 4 + 2] + f1.y * q[c * 4 + 3];
            }
            scr[j] = acc;
        }
        // serial softmax (no shuffles)
        float m = scr[0];
#pragma unroll
        for (int j = 1; j < 26; j++) m = fmaxf(m, scr[j]);
        float ssum = 0.f;
#pragma unroll
        for (int j = 0; j < 26; j++) { float e = expf(scr[j] - m); scr[j] = e; ssum += e; }
        float inv = 1.f / ssum;
        if (rowv) {
#pragma unroll
            for (int j = 0; j < 26; j++) pbuf[lane * 28 + j] = scr[j] * inv;
        }
        __syncwarp();

        // phase 2: d-parallel PV + residual + relu
        float vreg[26];
#pragma unroll
        for (int j = 0; j < 26; j++)
            vreg[j] = __bfloat162float(*(const __nv_bfloat16*)
                        (Qs + j * SQROWB + 256 + h * 64 + lane * 2));
        __nv_bfloat16* dst = Aout + (b0 + s) * ATTFLAT + h * DHEAD + lane;
#pragma unroll
        for (int i = 0; i < 26; i++) {
            float acc = __bfloat162float(*(const __nv_bfloat16*)
                          (Qs + i * SQROWB + 384 + h * 64 + lane * 2));
            const float* pr = &pbuf[i * 28];
#pragma unroll
            for (int j = 0; j < 24; j += 4) {
                float4 p4 = *(const float4*)&pr[j];
                acc += p4.x * vreg[j] + p4.y * vreg[j + 1]
                     + p4.z * vreg[j + 2] + p4.w * vreg[j + 3];
            }
            acc += pr[24] * vreg[24] + pr[25] * vreg[25];
            dst[(size_t)i * EDIM] = __float2bfloat16_rn(fmaxf(acc, 0.f));
        }
        __syncwarp();
    }
}

// ---------------- bf16 mma.sync GEMM (dnn layers) ----------------
template<int KTOT, int NTFULL, bool RELU, bool BF16OUT>
__global__ __launch_bounds__(256)
void gemm_mma(const __nv_bfloat16* __restrict__ A,
              const __nv_bfloat16* __restrict__ Bop,
              const float* __restrict__ bias,
              void* __restrict__ Cout) {
    __shared__ __align__(1024) unsigned char smA[128 * 128];
    __shared__ __align__(1024) unsigned char smB[128 * 128];
    const int tid = threadIdx.x;
    const int wid = tid >> 5, lane = tid & 31;
    const int wm = wid & 3, wn = wid >> 2;
    const long m0 = (long)blockIdx.x * 128;
    const int n0 = blockIdx.y * 128;

    float acc[2][8][4];
#pragma unroll
    for (int mi = 0; mi < 2; mi++)
#pragma unroll
        for (int ni = 0; ni < 8; ni++)
#pragma unroll
            for (int q = 0; q < 4; q++) acc[mi][ni][q] = 0.f;

    const uint32_t sA = smem_u32(smA), sB = smem_u32(smB);
    const int sel = lane >> 3, rr = lane & 7;
    const int arow0 = wm * 32 + (sel & 1) * 8 + rr;
    const int ahi = sel >> 1;
    const int brow0 = wn * 64 + (sel >> 1) * 8 + rr;
    const int bhi = sel & 1;

    const int NCH = KTOT / 64;
    for (int ch = 0; ch < NCH; ch++) {
        const unsigned char* Ag = (const unsigned char*)A + (m0 * KTOT + (long)ch * 64) * 2;
        const unsigned char* Bg = (const unsigned char*)Bop + (((long)n0 * KTOT) + (long)ch * 64) * 2;
#pragma unroll 2
        for (int u = tid; u < 1024; u += 256) {
            int r = u >> 3, ck = u & 7;
            uint32_t so = (uint32_t)(r * 128 + ((ck ^ (r & 7)) << 4));
            *(uint4*)(smA + so) = *(const uint4*)(Ag + (long)r * (KTOT * 2) + ck * 16);
            *(uint4*)(smB + so) = *(const uint4*)(Bg + (long)r * (KTOT * 2) + ck * 16);
        }
        __syncthreads();
#pragma unroll
        for (int kk = 0; kk < 4; kk++) {
            uint32_t a[2][4];
#pragma unroll
            for (int mi = 0; mi < 2; mi++) {
                int r = arow0 + mi * 16;
                LDSM_X4(a[mi], sA + r * 128 + ((uint32_t)((2 * kk + ahi) ^ (r & 7)) << 4));
            }
#pragma unroll
            for (int nip = 0; nip < 4; nip++) {
                int r = brow0 + nip * 16;
                uint32_t b[4];
                LDSM_X4(b, sB + r * 128 + ((uint32_t)((2 * kk + bhi) ^ (r & 7)) << 4));
#pragma unroll
                for (int mi = 0; mi < 2; mi++) {
                    mma_bf16(acc[mi][nip * 2],     a[mi], b[0], b[1]);
                    mma_bf16(acc[mi][nip * 2 + 1], a[mi], b[2], b[3]);
                }
            }
        }
        __syncthreads();
    }

    const int g = lane >> 2, t = lane & 3;
#pragma unroll
    for (int mi = 0; mi < 2; mi++) {
#pragma unroll
        for (int ni = 0; ni < 8; ni++) {
            int col = n0 + wn * 64 + ni * 8 + 2 * t;
            long r0 = m0 + wm * 32 + mi * 16 + g;
            float c0 = acc[mi][ni][0], c1 = acc[mi][ni][1];
            float c2 = acc[mi][ni][2], c3 = acc[mi][ni][3];
            if (bias != nullptr) {
                float bb0 = bias[col], bb1 = bias[col + 1];
                c0 += bb0; c1 += bb1; c2 += bb0; c3 += bb1;
            }
            if (RELU) {
                c0 = fmaxf(c0, 0.f); c1 = fmaxf(c1, 0.f);
                c2 = fmaxf(c2, 0.f); c3 = fmaxf(c3, 0.f);
            }
            if (BF16OUT) {
                __nv_bfloat16* base = (__nv_bfloat16*)Cout;
                *(__nv_bfloat162*)(base + r0 * NTFULL + col)       = __floats2bfloat162_rn(c0, c1);
                *(__nv_bfloat162*)(base + (r0 + 8) * NTFULL + col) = __floats2bfloat162_rn(c2, c3);
            } else {
                float* base = (float*)Cout;
                *(float2*)(base + r0 * NTFULL + col)       = make_float2(c0, c1);
                *(float2*)(base + (r0 + 8) * NTFULL + col) = make_float2(c2, c3);
            }
        }
    }
}

// ---------------- head ----------------
__global__ __launch_bounds__(256)
void head_kernel(const float* __restrict__ X,
                 const __nv_bfloat16* __restrict__ att,
                 const float* __restrict__ outW,
                 const float* __restrict__ linW, const float* __restrict__ linb,
                 float* __restrict__ out) {
    __shared__ __align__(16) float soW[STACKW];
    int tid = threadIdx.x;
    for (int i = tid; i < STACKW; i += 256) soW[i] = outW[i];
    __syncthreads();
    int warp = tid >> 5, lane = tid & 31;
    int s = blockIdx.x * 8 + warp;
    const uint4* ap = (const uint4*)(att + (size_t)s * ATTFLAT);
    float acc = 0.f;
#pragma unroll
    for (int t = 0; t < 7; t++) {
        int i = t * 32 + lane;
        if (t < 6 || lane < 16) {
            uint4 u = ap[i];
            const __nv_bfloat162* hb = (const __nv_bfloat162*)&u;
            const float* w = &soW[i * 8];
#pragma unroll
            for (int q = 0; q < 4; q++) {
                float2 f2 = __bfloat1622float2(hb[q]);
                acc += f2.x * w[2 * q] + f2.y * w[2 * q + 1];
            }
        }
    }
    {
        const float4* hp = (const float4*)&g_h2[(size_t)s * H2DIM];
        float4 a = hp[lane];
        const float4* ow4 = (const float4*)soW;
        float4 w = ow4[ATTFLAT / 4 + lane];
        acc += a.x * w.x + a.y * w.y + a.z * w.z + a.w * w.w;
    }
    float al = X[(size_t)s * XCOLS + lane] * linW[lane];
    if (lane < XCOLS - 32) al += X[(size_t)s * XCOLS + 32 + lane] * linW[32 + lane];
#pragma unroll
    for (int o = 16; o > 0; o >>= 1) {
        acc += __shfl_xor_sync(0xffffffffu, acc, o);
        al  += __shfl_xor_sync(0xffffffffu, al, o);
    }
    if (lane == 0) {
        float lin = fmaxf(al + linb[0], 0.f);
        out[s] = 1.f / (1.f + expf(-(lin + acc)));
    }
}

// ---------------- launcher ----------------
extern "C" void kernel_launch(void* const* d_in, const int* in_sizes, int n_in,
                              void* d_out, int out_size) {
    (void)in_sizes; (void)n_in; (void)out_size;
    const float* X    = (const float*)d_in[0];
    const int*   sidx = (const int*)  d_in[1];
    const float* emb  = (const float*)d_in[2];
    const float* Wq   = (const float*)d_in[3];
    const float* Wk   = (const float*)d_in[4];
    const float* Wv   = (const float*)d_in[5];
    const float* Wr   = (const float*)d_in[6];
    const float* W1   = (const float*)d_in[7];
    const float* b1   = (const float*)d_in[8];
    const float* W2   = (const float*)d_in[9];
    const float* b2   = (const float*)d_in[10];
    const float* outW = (const float*)d_in[11];
    const float* linW = (const float*)d_in[12];
    const float* linb = (const float*)d_in[13];
    float* out = (float*)d_out;

    void *pAttA, *pAttB, *pDnn, *pH1, *pH2, *pWqkvr, *pW1b, *pW2b;
    cudaGetSymbolAddress(&pAttA,  g_attA);
    cudaGetSymbolAddress(&pAttB,  g_attB);
    cudaGetSymbolAddress(&pDnn,   g_dnn_bf);
    cudaGetSymbolAddress(&pH1,    g_h1_bf);
    cudaGetSymbolAddress(&pH2,    g_h2);
    cudaGetSymbolAddress(&pWqkvr, g_wqkvr_bf);
    cudaGetSymbolAddress(&pW1b,   g_w1_bf);
    cudaGetSymbolAddress(&pW2b,   g_w2_bf);

    cudaFuncSetAttribute((const void*)fused_layer,
                         cudaFuncAttributeMaxDynamicSharedMemorySize, F_SMEM);

    prep_wqkvr<<<(NLAYER * QKVR_C * EDIM + 255) / 256, 256>>>(Wq, Wk, Wv, Wr);
    prep_w1<<<(H1DIM * KPAD + 255) / 256, 256>>>(W1);
    prep_w2<<<(H2DIM * H1DIM + 255) / 256, 256>>>(W2);
    gather_emb<<<MROWS / 8, 256>>>(sidx, emb);
    dense_pad<<<BATCH * 64 / 256, 256>>>(X);

    const __nv_bfloat16* wbase = (const __nv_bfloat16*)pWqkvr;
    fused_layer<<<BATCH / F_SPB, 256, F_SMEM>>>(
        (const __nv_bfloat16*)pDnn, (long)KPAD, wbase, (__nv_bfloat16*)pAttA);
    fused_layer<<<BATCH / F_SPB, 256, F_SMEM>>>(
        (const __nv_bfloat16*)pAttA, (long)ATTFLAT, wbase + (size_t)QKVR_C * EDIM,
        (__nv_bfloat16*)pAttB);
    fused_layer<<<BATCH / F_SPB, 256, F_SMEM>>>(
        (const __nv_bfloat16*)pAttB, (long)ATTFLAT, wbase + (size_t)2 * QKVR_C * EDIM,
        (__nv_bfloat16*)pAttA);

    gemm_mma<KPAD, H1DIM, true, true><<<dim3(BATCH / 128, H1DIM / 128), 256>>>(
        (const __nv_bfloat16*)pDnn, (const __nv_bfloat16*)pW1b, b1, pH1);
    gemm_mma<H1DIM, H2DIM, true, false><<<dim3(BATCH / 128, 1), 256>>>(
        (const __nv_bfloat16*)pH1, (const __nv_bfloat16*)pW2b, b2, pH2);
    head_kernel<<<BATCH / 8, 256>>>(X, (const __nv_bfloat16*)pAttA, outW, linW, linb, out);
}

// round 10
// speedup vs baseline: 2.7366x; 1.4837x over previous
#include <cuda_runtime.h>
#include <cuda_bf16.h>
#include <cstdint>
#include <math.h>

// ---------------- problem constants ----------------
#define BATCH     32768
#define NSPARSE   26
#define NDENSE    13
#define VOCAB     10000
#define EDIM      64
#define NHEAD     2
#define DHEAD     32
#define NLAYER    3
#define H1DIM     256
#define H2DIM     128
#define DNNIN     1677
#define KPAD      1728            // 27*64 ; dnn cols: [emb 0..1663 | dense | pad]
#define XCOLS     39
#define ATTFLAT   (NSPARSE*EDIM)  // 1664
#define QKVR_C    256
#define MROWS     (BATCH*NSPARSE)
#define STACKW    (ATTFLAT + H2DIM)

// ---------------- scratch ----------------
__device__ __nv_bfloat16  g_attA[(size_t)BATCH * ATTFLAT];
__device__ __nv_bfloat16  g_attB[(size_t)BATCH * ATTFLAT];
__device__ __nv_bfloat16  g_dnn_bf[(size_t)BATCH * KPAD];
__device__ __nv_bfloat16  g_h1_bf[(size_t)BATCH * H1DIM];
__device__ float          g_h2[(size_t)BATCH * H2DIM];
__device__ __nv_bfloat16  g_wqkvr_bf[NLAYER * QKVR_C * EDIM];  // [l][n][k]
__device__ __nv_bfloat16  g_w1_bf[H1DIM * KPAD];
__device__ __nv_bfloat16  g_w2_bf[H2DIM * H1DIM];

// ---------------- mma.sync helpers ----------------
__device__ __forceinline__ uint32_t smem_u32(const void* p) {
    uint32_t a;
    asm("{ .reg .u64 t; cvta.to.shared.u64 t, %1; cvt.u32.u64 %0, t; }" : "=r"(a) : "l"(p));
    return a;
}
#define LDSM_X4(d, addr) \
    asm volatile("ldmatrix.sync.aligned.m8n8.x4.shared.b16 {%0,%1,%2,%3}, [%4];" \
        : "=r"((d)[0]), "=r"((d)[1]), "=r"((d)[2]), "=r"((d)[3]) : "r"(addr))

__device__ __forceinline__ void mma_bf16(float* c, const uint32_t* a,
                                         uint32_t b0, uint32_t b1) {
    asm volatile(
        "mma.sync.aligned.m16n8k16.row.col.f32.bf16.bf16.f32 "
        "{%0,%1,%2,%3},{%4,%5,%6,%7},{%8,%9},{%0,%1,%2,%3};"
        : "+f"(c[0]), "+f"(c[1]), "+f"(c[2]), "+f"(c[3])
        : "r"(a[0]), "r"(a[1]), "r"(a[2]), "r"(a[3]), "r"(b0), "r"(b1));
}

// ---------------- merged weight prep (fp32 -> bf16 [N][K]) ----------------
#define PREP_W1_OFF  (NLAYER * QKVR_C * EDIM)            // 49152
#define PREP_W2_OFF  (PREP_W1_OFF + H1DIM * KPAD)        // 491520
#define PREP_TOTAL   (PREP_W2_OFF + H2DIM * H1DIM)       // 524288
__global__ __launch_bounds__(256)
void prep_all(const float* __restrict__ Wq, const float* __restrict__ Wk,
              const float* __restrict__ Wv, const float* __restrict__ Wr,
              const float* __restrict__ W1, const float* __restrict__ W2) {
    int idx = blockIdx.x * 256 + threadIdx.x;
    if (idx < PREP_W1_OFF) {
        int l = idx >> 14, rem = idx & 16383;
        int n = rem >> 6, k = rem & 63;
        const float* Ws[4] = {Wq, Wk, Wv, Wr};
        g_wqkvr_bf[idx] = __float2bfloat16_rn(Ws[n >> 6][(l * EDIM + k) * EDIM + (n & 63)]);
    } else if (idx < PREP_W2_OFF) {
        int j = idx - PREP_W1_OFF;
        int n = j / KPAD, k = j % KPAD;
        float v = 0.f;
        if (k < ATTFLAT)               v = W1[(long)(13 + k) * H1DIM + n];
        else if (k < ATTFLAT + NDENSE) v = W1[(long)(k - ATTFLAT) * H1DIM + n];
        g_w1_bf[j] = __float2bfloat16_rn(v);
    } else {
        int j = idx - PREP_W2_OFF;
        int n = j / H1DIM, k = j % H1DIM;
        g_w2_bf[j] = __float2bfloat16_rn(W2[(long)k * H2DIM + n]);
    }
}

// ---------------- embedding gather: 8 threads/row, 2x float4 per thread ----
__global__ __launch_bounds__(256)
void gather_emb(const int* __restrict__ sidx, const float* __restrict__ emb) {
    int t = threadIdx.x;
    int row = blockIdx.x * 32 + (t >> 3);       // b*26 + f
    int qi  = t & 7;                            // 8-float chunk within row
    int b = row / NSPARSE, f = row - b * NSPARSE;
    int vrow = sidx[(long)b * NSPARSE + f];
    const float* src = emb + ((long)f * VOCAB + vrow) * EDIM + qi * 8;
    float4 a0 = *(const float4*)src;
    float4 a1 = *(const float4*)(src + 4);
    __nv_bfloat162 h0 = __floats2bfloat162_rn(a0.x, a0.y);
    __nv_bfloat162 h1 = __floats2bfloat162_rn(a0.z, a0.w);
    __nv_bfloat162 h2 = __floats2bfloat162_rn(a1.x, a1.y);
    __nv_bfloat162 h3 = __floats2bfloat162_rn(a1.z, a1.w);
    uint4 o;
    o.x = *(uint32_t*)&h0; o.y = *(uint32_t*)&h1;
    o.z = *(uint32_t*)&h2; o.w = *(uint32_t*)&h3;
    *(uint4*)(g_dnn_bf + (long)b * KPAD + f * EDIM + qi * 8) = o;
}
__global__ __launch_bounds__(256)
void dense_pad(const float* __restrict__ X) {
    long idx = (long)blockIdx.x * 256 + threadIdx.x;
    int b = (int)(idx >> 6), cc = (int)(idx & 63);
    float v = (cc < NDENSE) ? X[(long)b * XCOLS + NSPARSE + cc] : 0.f;
    g_dnn_bf[(long)b * KPAD + ATTFLAT + cc] = __float2bfloat16_rn(v);
}

// ---------------- fused proj + attention layer ----------------
// 256 threads, 4 samples/CTA (104 A-rows, 7 m16 tiles incl. zero-pad rows).
// Warp w: mma for qkvr cols [32w,32w+32), then attention task (s=w>>1, h=w&1).
// smem ~104 KB -> 2 CTAs/SM.
#define F_SPB   4
#define SQROWB  528
#define OFF_W   0
#define OFF_A   32768
#define OFF_Q   (OFF_A + 112 * 128)            // 47104
#define F_SMEM  (OFF_Q + 112 * SQROWB)         // 106240

__global__ __launch_bounds__(256)
void fused_layer(const __nv_bfloat16* __restrict__ Ain, long sstride,
                 const __nv_bfloat16* __restrict__ W,
                 __nv_bfloat16* __restrict__ Aout) {
    extern __shared__ __align__(1024) unsigned char sm[];
    const int tid = threadIdx.x, wid = tid >> 5, lane = tid & 31;
    const long b0 = (long)blockIdx.x * F_SPB;

    // W tile: 256 rows x 128 B, swizzled
    const unsigned char* Wg = (const unsigned char*)W;
#pragma unroll 4
    for (int u = tid; u < 2048; u += 256) {
        int r = u >> 3, ck = u & 7;
        *(uint4*)(sm + OFF_W + r * 128 + ((ck ^ (r & 7)) << 4)) =
            *(const uint4*)(Wg + (long)r * 128 + ck * 16);
    }
    // A tile: 112 rows x 128 B (rows 104..111 zero), swizzled
#pragma unroll 4
    for (int u = tid; u < 896; u += 256) {
        int r = u >> 3, ck = u & 7;
        uint4 v = make_uint4(0u, 0u, 0u, 0u);
        if (r < 104) {
            int s = r / 26, f = r - s * 26;
            v = *(const uint4*)((const unsigned char*)(Ain + (b0 + s) * sstride + f * EDIM) + ck * 16);
        }
        *(uint4*)(sm + OFF_A + r * 128 + ((ck ^ (r & 7)) << 4)) = v;
    }
    __syncthreads();

    const uint32_t sA = smem_u32(sm + OFF_A);
    const uint32_t sW = smem_u32(sm + OFF_W);
    const int sel = lane >> 3, rr = lane & 7;
    const int g = lane >> 2, t4 = lane & 3;

    // B fragments for this warp's 32 cols: 4 k-steps x 2 n16 tiles
    uint32_t bfr[4][2][4];
#pragma unroll
    for (int kk = 0; kk < 4; kk++)
#pragma unroll
        for (int nip = 0; nip < 2; nip++) {
            int rb = wid * 32 + nip * 16 + (sel >> 1) * 8 + rr;
            LDSM_X4(bfr[kk][nip],
                    sW + rb * 128 + ((uint32_t)((2 * kk + (sel & 1)) ^ (rb & 7)) << 4));
        }

    // 7 m-tiles of 16 rows
    for (int mt = 0; mt < 7; mt++) {
        float acc[4][4];
#pragma unroll
        for (int ni = 0; ni < 4; ni++)
#pragma unroll
            for (int q = 0; q < 4; q++) acc[ni][q] = 0.f;
#pragma unroll
        for (int kk = 0; kk < 4; kk++) {
            uint32_t a[4];
            int ra = mt * 16 + (sel & 1) * 8 + rr;
            LDSM_X4(a, sA + ra * 128 + ((uint32_t)((2 * kk + (sel >> 1)) ^ (ra & 7)) << 4));
#pragma unroll
            for (int nip = 0; nip < 2; nip++) {
                mma_bf16(acc[nip * 2],     a, bfr[kk][nip][0], bfr[kk][nip][1]);
                mma_bf16(acc[nip * 2 + 1], a, bfr[kk][nip][2], bfr[kk][nip][3]);
            }
        }
#pragma unroll
        for (int ni = 0; ni < 4; ni++) {
            int col = wid * 32 + ni * 8 + 2 * t4;
            int r0 = mt * 16 + g;
            *(__nv_bfloat162*)(sm + OFF_Q + (long)r0 * SQROWB + col * 2) =
                __floats2bfloat162_rn(acc[ni][0], acc[ni][1]);
            *(__nv_bfloat162*)(sm + OFF_Q + (long)(r0 + 8) * SQROWB + col * 2) =
                __floats2bfloat162_rn(acc[ni][2], acc[ni][3]);
        }
    }
    __syncthreads();

    // attention: warp w -> (s = w>>1, h = w&1). p-buffer overlays W region.
    const int s = wid >> 1, h = wid & 1;
    const unsigned char* Qs = sm + OFF_Q + (long)s * 26 * SQROWB;
    float* pbuf = (float*)(sm + wid * 2944);
    const bool rowv = (lane < NSPARSE);

    // phase 1: lane i owns score row i
    float q[32];
    if (rowv) {
#pragma unroll
        for (int c = 0; c < 8; c++) {
            uint2 u = *(const uint2*)(Qs + lane * SQROWB + h * 64 + c * 8);
            const __nv_bfloat162* hb = (const __nv_bfloat162*)&u;
            float2 f0 = __bfloat1622float2(hb[0]);
            float2 f1 = __bfloat1622float2(hb[1]);
            q[c * 4] = f0.x; q[c * 4 + 1] = f0.y; q[c * 4 + 2] = f1.x; q[c * 4 + 3] = f1.y;
        }
    } else {
#pragma unroll
        for (int d = 0; d < 32; d++) q[d] = 0.f;
    }
    float scr[26];
#pragma unroll
    for (int j = 0; j < 26; j++) {
        float acc = 0.f;
#pragma unroll
        for (int c = 0; c < 8; c++) {
            uint2 u = *(const uint2*)(Qs + j * SQROWB + 128 + h * 64 + c * 8);  // k_j broadcast
            const __nv_bfloat162* hb = (const __nv_bfloat162*)&u;
            float2 f0 = __bfloat1622float2(hb[0]);
            float2 f1 = __bfloat1622float2(hb[1]);
            acc += f0.x * q[c * 4] + f0.y * q[c * 4 + 1]
                 + f1.x * q[c * 4 + 2] + f1.y * q[c * 4 + 3];
        }
        scr[j] = acc;
    }
    float m = scr[0];
#pragma unroll
    for (int j = 1; j < 26; j++) m = fmaxf(m, scr[j]);
    float ssum = 0.f;
#pragma unroll
    for (int j = 0; j < 26; j++) { float e = expf(scr[j] - m); scr[j] = e; ssum += e; }
    float inv = 1.f / ssum;
    if (rowv) {
#pragma unroll
        for (int j = 0; j < 26; j++) pbuf[lane * 28 + j] = scr[j] * inv;
    }
    __syncwarp();

    // phase 2: d-parallel PV + residual + relu
    float vreg[26];
#pragma unroll
    for (int j = 0; j < 26; j++)
        vreg[j] = __bfloat162float(*(const __nv_bfloat16*)
                    (Qs + j * SQROWB + 256 + h * 64 + lane * 2));
    __nv_bfloat16* dst = Aout + (b0 + s) * ATTFLAT + h * DHEAD + lane;
#pragma unroll
    for (int i = 0; i < 26; i++) {
        float acc = __bfloat162float(*(const __nv_bfloat16*)
                      (Qs + i * SQROWB + 384 + h * 64 + lane * 2));
        const float* pr = &pbuf[i * 28];
#pragma unroll
        for (int j = 0; j < 24; j += 4) {
            float4 p4 = *(const float4*)&pr[j];
            acc += p4.x * vreg[j] + p4.y * vreg[j + 1]
                 + p4.z * vreg[j + 2] + p4.w * vreg[j + 3];
        }
        acc += pr[24] * vreg[24] + pr[25] * vreg[25];
        dst[(size_t)i * EDIM] = __float2bfloat16_rn(fmaxf(acc, 0.f));
    }
}

// ---------------- bf16 mma.sync GEMM (dnn layers) ----------------
template<int KTOT, int NTFULL, bool RELU, bool BF16OUT>
__global__ __launch_bounds__(256)
void gemm_mma(const __nv_bfloat16* __restrict__ A,
              const __nv_bfloat16* __restrict__ Bop,
              const float* __restrict__ bias,
              void* __restrict__ Cout) {
    __shared__ __align__(1024) unsigned char smA[128 * 128];
    __shared__ __align__(1024) unsigned char smB[128 * 128];
    const int tid = threadIdx.x;
    const int wid = tid >> 5, lane = tid & 31;
    const int wm = wid & 3, wn = wid >> 2;
    const long m0 = (long)blockIdx.x * 128;
    const int n0 = blockIdx.y * 128;

    float acc[2][8][4];
#pragma unroll
    for (int mi = 0; mi < 2; mi++)
#pragma unroll
        for (int ni = 0; ni < 8; ni++)
#pragma unroll
            for (int q = 0; q < 4; q++) acc[mi][ni][q] = 0.f;

    const uint32_t sA = smem_u32(smA), sB = smem_u32(smB);
    const int sel = lane >> 3, rr = lane & 7;
    const int arow0 = wm * 32 + (sel & 1) * 8 + rr;
    const int ahi = sel >> 1;
    const int brow0 = wn * 64 + (sel >> 1) * 8 + rr;
    const int bhi = sel & 1;

    const int NCH = KTOT / 64;
    for (int ch = 0; ch < NCH; ch++) {
        const unsigned char* Ag = (const unsigned char*)A + (m0 * KTOT + (long)ch * 64) * 2;
        const unsigned char* Bg = (const unsigned char*)Bop + (((long)n0 * KTOT) + (long)ch * 64) * 2;
#pragma unroll 2
        for (int u = tid; u < 1024; u += 256) {
            int r = u >> 3, ck = u & 7;
            uint32_t so = (uint32_t)(r * 128 + ((ck ^ (r & 7)) << 4));
            *(uint4*)(smA + so) = *(const uint4*)(Ag + (long)r * (KTOT * 2) + ck * 16);
            *(uint4*)(smB + so) = *(const uint4*)(Bg + (long)r * (KTOT * 2) + ck * 16);
        }
        __syncthreads();
#pragma unroll
        for (int kk = 0; kk < 4; kk++) {
            uint32_t a[2][4];
#pragma unroll
            for (int mi = 0; mi < 2; mi++) {
                int r = arow0 + mi * 16;
                LDSM_X4(a[mi], sA + r * 128 + ((uint32_t)((2 * kk + ahi) ^ (r & 7)) << 4));
            }
#pragma unroll
            for (int nip = 0; nip < 4; nip++) {
                int r = brow0 + nip * 16;
                uint32_t b[4];
                LDSM_X4(b, sB + r * 128 + ((uint32_t)((2 * kk + bhi) ^ (r & 7)) << 4));
#pragma unroll
                for (int mi = 0; mi < 2; mi++) {
                    mma_bf16(acc[mi][nip * 2],     a[mi], b[0], b[1]);
                    mma_bf16(acc[mi][nip * 2 + 1], a[mi], b[2], b[3]);
                }
            }
        }
        __syncthreads();
    }

    const int g = lane >> 2, t = lane & 3;
#pragma unroll
    for (int mi = 0; mi < 2; mi++) {
#pragma unroll
        for (int ni = 0; ni < 8; ni++) {
            int col = n0 + wn * 64 + ni * 8 + 2 * t;
            long r0 = m0 + wm * 32 + mi * 16 + g;
            float c0 = acc[mi][ni][0], c1 = acc[mi][ni][1];
            float c2 = acc[mi][ni][2], c3 = acc[mi][ni][3];
            if (bias != nullptr) {
                float bb0 = bias[col], bb1 = bias[col + 1];
                c0 += bb0; c1 += bb1; c2 += bb0; c3 += bb1;
            }
            if (RELU) {
                c0 = fmaxf(c0, 0.f); c1 = fmaxf(c1, 0.f);
                c2 = fmaxf(c2, 0.f); c3 = fmaxf(c3, 0.f);
            }
            if (BF16OUT) {
                __nv_bfloat16* base = (__nv_bfloat16*)Cout;
                *(__nv_bfloat162*)(base + r0 * NTFULL + col)       = __floats2bfloat162_rn(c0, c1);
                *(__nv_bfloat162*)(base + (r0 + 8) * NTFULL + col) = __floats2bfloat162_rn(c2, c3);
            } else {
                float* base = (float*)Cout;
                *(float2*)(base + r0 * NTFULL + col)       = make_float2(c0, c1);
                *(float2*)(base + (r0 + 8) * NTFULL + col) = make_float2(c2, c3);
            }
        }
    }
}

// ---------------- head ----------------
__global__ __launch_bounds__(256)
void head_kernel(const float* __restrict__ X,
                 const __nv_bfloat16* __restrict__ att,
                 const float* __restrict__ outW,
                 const float* __restrict__ linW, const float* __restrict__ linb,
                 float* __restrict__ out) {
    __shared__ __align__(16) float soW[STACKW];
    int tid = threadIdx.x;
    for (int i = tid; i < STACKW; i += 256) soW[i] = outW[i];
    __syncthreads();
    int warp = tid >> 5, lane = tid & 31;
    int s = blockIdx.x * 8 + warp;
    const uint4* ap = (const uint4*)(att + (size_t)s * ATTFLAT);
    float acc = 0.f;
#pragma unroll
    for (int t = 0; t < 7; t++) {
        int i = t * 32 + lane;
        if (t < 6 || lane < 16) {
            uint4 u = ap[i];
            const __nv_bfloat162* hb = (const __nv_bfloat162*)&u;
            const float* w = &soW[i * 8];
#pragma unroll
            for (int q = 0; q < 4; q++) {
                float2 f2 = __bfloat1622float2(hb[q]);
                acc += f2.x * w[2 * q] + f2.y * w[2 * q + 1];
            }
        }
    }
    {
        const float4* hp = (const float4*)&g_h2[(size_t)s * H2DIM];
        float4 a = hp[lane];
        const float4* ow4 = (const float4*)soW;
        float4 w = ow4[ATTFLAT / 4 + lane];
        acc += a.x * w.x + a.y * w.y + a.z * w.z + a.w * w.w;
    }
    float al = X[(size_t)s * XCOLS + lane] * linW[lane];
    if (lane < XCOLS - 32) al += X[(size_t)s * XCOLS + 32 + lane] * linW[32 + lane];
#pragma unroll
    for (int o = 16; o > 0; o >>= 1) {
        acc += __shfl_xor_sync(0xffffffffu, acc, o);
        al  += __shfl_xor_sync(0xffffffffu, al, o);
    }
    if (lane == 0) {
        float lin = fmaxf(al + linb[0], 0.f);
        out[s] = 1.f / (1.f + expf(-(lin + acc)));
    }
}

// ---------------- launcher ----------------
extern "C" void kernel_launch(void* const* d_in, const int* in_sizes, int n_in,
                              void* d_out, int out_size) {
    (void)in_sizes; (void)n_in; (void)out_size;
    const float* X    = (const float*)d_in[0];
    const int*   sidx = (const int*)  d_in[1];
    const float* emb  = (const float*)d_in[2];
    const float* Wq   = (const float*)d_in[3];
    const float* Wk   = (const float*)d_in[4];
    const float* Wv   = (const float*)d_in[5];
    const float* Wr   = (const float*)d_in[6];
    const float* W1   = (const float*)d_in[7];
    const float* b1   = (const float*)d_in[8];
    const float* W2   = (const float*)d_in[9];
    const float* b2   = (const float*)d_in[10];
    const float* outW = (const float*)d_in[11];
    const float* linW = (const float*)d_in[12];
    const float* linb = (const float*)d_in[13];
    float* out = (float*)d_out;

    void *pAttA, *pAttB, *pDnn, *pH1, *pH2, *pWqkvr, *pW1b, *pW2b;
    cudaGetSymbolAddress(&pAttA,  g_attA);
    cudaGetSymbolAddress(&pAttB,  g_attB);
    cudaGetSymbolAddress(&pDnn,   g_dnn_bf);
    cudaGetSymbolAddress(&pH1,    g_h1_bf);
    cudaGetSymbolAddress(&pH2,    g_h2);
    cudaGetSymbolAddress(&pWqkvr, g_wqkvr_bf);
    cudaGetSymbolAddress(&pW1b,   g_w1_bf);
    cudaGetSymbolAddress(&pW2b,   g_w2_bf);

    cudaFuncSetAttribute((const void*)fused_layer,
                         cudaFuncAttributeMaxDynamicSharedMemorySize, F_SMEM);

    prep_all<<<PREP_TOTAL / 256, 256>>>(Wq, Wk, Wv, Wr, W1, W2);
    gather_emb<<<MROWS / 32, 256>>>(sidx, emb);
    dense_pad<<<BATCH * 64 / 256, 256>>>(X);

    const __nv_bfloat16* wbase = (const __nv_bfloat16*)pWqkvr;
    fused_layer<<<BATCH / F_SPB, 256, F_SMEM>>>(
        (const __nv_bfloat16*)pDnn, (long)KPAD, wbase, (__nv_bfloat16*)pAttA);
    fused_layer<<<BATCH / F_SPB, 256, F_SMEM>>>(
        (const __nv_bfloat16*)pAttA, (long)ATTFLAT, wbase + (size_t)QKVR_C * EDIM,
        (__nv_bfloat16*)pAttB);
    fused_layer<<<BATCH / F_SPB, 256, F_SMEM>>>(
        (const __nv_bfloat16*)pAttB, (long)ATTFLAT, wbase + (size_t)2 * QKVR_C * EDIM,
        (__nv_bfloat16*)pAttA);

    gemm_mma<KPAD, H1DIM, true, true><<<dim3(BATCH / 128, H1DIM / 128), 256>>>(
        (const __nv_bfloat16*)pDnn, (const __nv_bfloat16*)pW1b, b1, pH1);
    gemm_mma<H1DIM, H2DIM, true, false><<<dim3(BATCH / 128, 1), 256>>>(
        (const __nv_bfloat16*)pH1, (const __nv_bfloat16*)pW2b, b2, pH2);
    head_kernel<<<BATCH / 8, 256>>>(X, (const __nv_bfloat16*)pAttA, outW, linW, linb, out);
}

// round 11
// speedup vs baseline: 4.6065x; 1.6833x over previous
#include <cuda_runtime.h>
#include <cuda_bf16.h>
#include <cstdint>
#include <math.h>

// ---------------- problem constants ----------------
#define BATCH     32768
#define NSPARSE   26
#define NDENSE    13
#define VOCAB     10000
#define EDIM      64
#define NHEAD     2
#define DHEAD     32
#define NLAYER    3
#define H1DIM     256
#define H2DIM     128
#define DNNIN     1677
#define KPAD      1728            // 27*64 ; dnn cols: [emb 0..1663 | dense | pad]
#define XCOLS     39
#define ATTFLAT   (NSPARSE*EDIM)  // 1664
#define QKVR_C    256
#define MROWS     (BATCH*NSPARSE)
#define STACKW    (ATTFLAT + H2DIM)

// ---------------- scratch ----------------
__device__ __nv_bfloat16  g_attA[(size_t)BATCH * ATTFLAT];
__device__ __nv_bfloat16  g_attB[(size_t)BATCH * ATTFLAT];
__device__ __nv_bfloat16  g_dnn_bf[(size_t)BATCH * KPAD];
__device__ __nv_bfloat16  g_h1_bf[(size_t)BATCH * H1DIM];
__device__ float          g_h2[(size_t)BATCH * H2DIM];
__device__ __nv_bfloat16  g_wqkvr_bf[NLAYER * QKVR_C * EDIM];  // [l][n][k]
__device__ __nv_bfloat16  g_w1_bf[H1DIM * KPAD];
__device__ __nv_bfloat16  g_w2_bf[H2DIM * H1DIM];

// ---------------- mma.sync helpers ----------------
__device__ __forceinline__ uint32_t smem_u32(const void* p) {
    uint32_t a;
    asm("{ .reg .u64 t; cvta.to.shared.u64 t, %1; cvt.u32.u64 %0, t; }" : "=r"(a) : "l"(p));
    return a;
}
#define LDSM_X4(d, addr) \
    asm volatile("ldmatrix.sync.aligned.m8n8.x4.shared.b16 {%0,%1,%2,%3}, [%4];" \
        : "=r"((d)[0]), "=r"((d)[1]), "=r"((d)[2]), "=r"((d)[3]) : "r"(addr))
#define LDSM_X4_T(d, addr) \
    asm volatile("ldmatrix.sync.aligned.m8n8.x4.trans.shared.b16 {%0,%1,%2,%3}, [%4];" \
        : "=r"((d)[0]), "=r"((d)[1]), "=r"((d)[2]), "=r"((d)[3]) : "r"(addr))

__device__ __forceinline__ void mma_bf16(float* c, const uint32_t* a,
                                         uint32_t b0, uint32_t b1) {
    asm volatile(
        "mma.sync.aligned.m16n8k16.row.col.f32.bf16.bf16.f32 "
        "{%0,%1,%2,%3},{%4,%5,%6,%7},{%8,%9},{%0,%1,%2,%3};"
        : "+f"(c[0]), "+f"(c[1]), "+f"(c[2]), "+f"(c[3])
        : "r"(a[0]), "r"(a[1]), "r"(a[2]), "r"(a[3]), "r"(b0), "r"(b1));
}
__device__ __forceinline__ uint32_t packbf(float a, float b) {
    __nv_bfloat162 h = __floats2bfloat162_rn(a, b);
    return *(uint32_t*)&h;
}

// ---------------- merged weight prep ----------------
#define PREP_W1_OFF  (NLAYER * QKVR_C * EDIM)
#define PREP_W2_OFF  (PREP_W1_OFF + H1DIM * KPAD)
#define PREP_TOTAL   (PREP_W2_OFF + H2DIM * H1DIM)
__global__ __launch_bounds__(256)
void prep_all(const float* __restrict__ Wq, const float* __restrict__ Wk,
              const float* __restrict__ Wv, const float* __restrict__ Wr,
              const float* __restrict__ W1, const float* __restrict__ W2) {
    int idx = blockIdx.x * 256 + threadIdx.x;
    if (idx < PREP_W1_OFF) {
        int l = idx >> 14, rem = idx & 16383;
        int n = rem >> 6, k = rem & 63;
        const float* Ws[4] = {Wq, Wk, Wv, Wr};
        g_wqkvr_bf[idx] = __float2bfloat16_rn(Ws[n >> 6][(l * EDIM + k) * EDIM + (n & 63)]);
    } else if (idx < PREP_W2_OFF) {
        int j = idx - PREP_W1_OFF;
        int n = j / KPAD, k = j % KPAD;
        float v = 0.f;
        if (k < ATTFLAT)               v = W1[(long)(13 + k) * H1DIM + n];
        else if (k < ATTFLAT + NDENSE) v = W1[(long)(k - ATTFLAT) * H1DIM + n];
        g_w1_bf[j] = __float2bfloat16_rn(v);
    } else {
        int j = idx - PREP_W2_OFF;
        int n = j / H1DIM, k = j % H1DIM;
        g_w2_bf[j] = __float2bfloat16_rn(W2[(long)k * H2DIM + n]);
    }
}

// ---------------- embedding gather ----------------
__global__ __launch_bounds__(256)
void gather_emb(const int* __restrict__ sidx, const float* __restrict__ emb) {
    int t = threadIdx.x;
    int row = blockIdx.x * 32 + (t >> 3);
    int qi  = t & 7;
    int b = row / NSPARSE, f = row - b * NSPARSE;
    int vrow = sidx[(long)b * NSPARSE + f];
    const float* src = emb + ((long)f * VOCAB + vrow) * EDIM + qi * 8;
    float4 a0 = *(const float4*)src;
    float4 a1 = *(const float4*)(src + 4);
    uint4 o;
    o.x = packbf(a0.x, a0.y); o.y = packbf(a0.z, a0.w);
    o.z = packbf(a1.x, a1.y); o.w = packbf(a1.z, a1.w);
    *(uint4*)(g_dnn_bf + (long)b * KPAD + f * EDIM + qi * 8) = o;
}
__global__ __launch_bounds__(256)
void dense_pad(const float* __restrict__ X) {
    long idx = (long)blockIdx.x * 256 + threadIdx.x;
    int b = (int)(idx >> 6), cc = (int)(idx & 63);
    float v = (cc < NDENSE) ? X[(long)b * XCOLS + NSPARSE + cc] : 0.f;
    g_dnn_bf[(long)b * KPAD + ATTFLAT + cc] = __float2bfloat16_rn(v);
}

// ---------------- fused proj + attention layer (tensor-core attention) ----
// 256 threads, 4 samples/CTA. Warp w: mma for qkvr cols [32w,32w+32),
// then attention task (s=w>>1, h=w&1) fully on mma.sync.
#define F_SPB   4
#define SQROWB  528
#define OFF_W   0
#define OFF_A   32768
#define OFF_Q   (OFF_A + 112 * 128)            // 47104
#define F_SMEM  (OFF_Q + 112 * SQROWB)         // 106240

__global__ __launch_bounds__(256)
void fused_layer(const __nv_bfloat16* __restrict__ Ain, long sstride,
                 const __nv_bfloat16* __restrict__ W,
                 __nv_bfloat16* __restrict__ Aout) {
    extern __shared__ __align__(1024) unsigned char sm[];
    const int tid = threadIdx.x, wid = tid >> 5, lane = tid & 31;
    const long b0 = (long)blockIdx.x * F_SPB;

    // W tile: 256 rows x 128 B, swizzled
    const unsigned char* Wg = (const unsigned char*)W;
#pragma unroll 4
    for (int u = tid; u < 2048; u += 256) {
        int r = u >> 3, ck = u & 7;
        *(uint4*)(sm + OFF_W + r * 128 + ((ck ^ (r & 7)) << 4)) =
            *(const uint4*)(Wg + (long)r * 128 + ck * 16);
    }
    // A tile: 112 rows x 128 B (rows 104..111 zero), swizzled
#pragma unroll 4
    for (int u = tid; u < 896; u += 256) {
        int r = u >> 3, ck = u & 7;
        uint4 v = make_uint4(0u, 0u, 0u, 0u);
        if (r < 104) {
            int s = r / 26, f = r - s * 26;
            v = *(const uint4*)((const unsigned char*)(Ain + (b0 + s) * sstride + f * EDIM) + ck * 16);
        }
        *(uint4*)(sm + OFF_A + r * 128 + ((ck ^ (r & 7)) << 4)) = v;
    }
    __syncthreads();

    const uint32_t sA = smem_u32(sm + OFF_A);
    const uint32_t sW = smem_u32(sm + OFF_W);
    const int sel = lane >> 3, rr = lane & 7;
    const int g = lane >> 2, t4 = lane & 3;

    // B fragments for this warp's 32 cols
    uint32_t bfr[4][2][4];
#pragma unroll
    for (int kk = 0; kk < 4; kk++)
#pragma unroll
        for (int nip = 0; nip < 2; nip++) {
            int rb = wid * 32 + nip * 16 + (sel >> 1) * 8 + rr;
            LDSM_X4(bfr[kk][nip],
                    sW + rb * 128 + ((uint32_t)((2 * kk + (sel & 1)) ^ (rb & 7)) << 4));
        }
    // 7 m-tiles of 16 rows
    for (int mt = 0; mt < 7; mt++) {
        float acc[4][4];
#pragma unroll
        for (int ni = 0; ni < 4; ni++)
#pragma unroll
            for (int q = 0; q < 4; q++) acc[ni][q] = 0.f;
#pragma unroll
        for (int kk = 0; kk < 4; kk++) {
            uint32_t a[4];
            int ra = mt * 16 + (sel & 1) * 8 + rr;
            LDSM_X4(a, sA + ra * 128 + ((uint32_t)((2 * kk + (sel >> 1)) ^ (ra & 7)) << 4));
#pragma unroll
            for (int nip = 0; nip < 2; nip++) {
                mma_bf16(acc[nip * 2],     a, bfr[kk][nip][0], bfr[kk][nip][1]);
                mma_bf16(acc[nip * 2 + 1], a, bfr[kk][nip][2], bfr[kk][nip][3]);
            }
        }
#pragma unroll
        for (int ni = 0; ni < 4; ni++) {
            int col = wid * 32 + ni * 8 + 2 * t4;
            int r0 = mt * 16 + g;
            *(uint32_t*)(sm + OFF_Q + (long)r0 * SQROWB + col * 2) = packbf(acc[ni][0], acc[ni][1]);
            *(uint32_t*)(sm + OFF_Q + (long)(r0 + 8) * SQROWB + col * 2) = packbf(acc[ni][2], acc[ni][3]);
        }
    }
    __syncthreads();

    // ---------- attention on tensor cores: warp -> (s = w>>1, h = w&1) ----
    const int s = wid >> 1, h = wid & 1;
    const uint32_t sQ = smem_u32(sm + OFF_Q) + (uint32_t)(s * 26 * SQROWB);

    // scores S[32,32] (rows/cols >=26 garbage/masked)
    float sc[2][4][4];
#pragma unroll
    for (int mt = 0; mt < 2; mt++)
#pragma unroll
        for (int nt = 0; nt < 4; nt++)
#pragma unroll
            for (int q = 0; q < 4; q++) sc[mt][nt][q] = 0.f;

#pragma unroll
    for (int ks = 0; ks < 2; ks++) {
        uint32_t qf[2][4];
#pragma unroll
        for (int mt = 0; mt < 2; mt++) {
            int r = mt * 16 + (sel & 1) * 8 + rr;
            LDSM_X4(qf[mt], sQ + (uint32_t)(r * SQROWB + h * 64 + ks * 32 + (sel >> 1) * 16));
        }
#pragma unroll
        for (int ntp = 0; ntp < 2; ntp++) {
            int jn = ntp * 16 + (sel >> 1) * 8 + rr;
            uint32_t kf[4];
            LDSM_X4(kf, sQ + (uint32_t)(jn * SQROWB + 128 + h * 64 + ks * 32 + (sel & 1) * 16));
#pragma unroll
            for (int mt = 0; mt < 2; mt++) {
                mma_bf16(sc[mt][ntp * 2],     qf[mt], kf[0], kf[1]);
                mma_bf16(sc[mt][ntp * 2 + 1], qf[mt], kf[2], kf[3]);
            }
        }
    }
    // mask cols >= 26 (nt=3: cols 24 + 2*t4 + {0,1})
#pragma unroll
    for (int mt = 0; mt < 2; mt++)
#pragma unroll
        for (int q = 0; q < 4; q++) {
            int col = 24 + 2 * t4 + (q & 1);
            if (col >= 26) sc[mt][3][q] = -INFINITY;
        }
    // softmax per row (rows g and g+8 per m-tile); reduce in-lane then over quad
#pragma unroll
    for (int mt = 0; mt < 2; mt++) {
#pragma unroll
        for (int half = 0; half < 2; half++) {
            float m = -INFINITY;
#pragma unroll
            for (int nt = 0; nt < 4; nt++)
                m = fmaxf(m, fmaxf(sc[mt][nt][half * 2], sc[mt][nt][half * 2 + 1]));
            m = fmaxf(m, __shfl_xor_sync(0xffffffffu, m, 1));
            m = fmaxf(m, __shfl_xor_sync(0xffffffffu, m, 2));
            float ssum = 0.f;
#pragma unroll
            for (int nt = 0; nt < 4; nt++) {
                float e0 = __expf(sc[mt][nt][half * 2] - m);
                float e1 = __expf(sc[mt][nt][half * 2 + 1] - m);
                sc[mt][nt][half * 2] = e0; sc[mt][nt][half * 2 + 1] = e1;
                ssum += e0 + e1;
            }
            ssum += __shfl_xor_sync(0xffffffffu, ssum, 1);
            ssum += __shfl_xor_sync(0xffffffffu, ssum, 2);
            float inv = 1.f / ssum;
#pragma unroll
            for (int nt = 0; nt < 4; nt++) {
                sc[mt][nt][half * 2] *= inv;
                sc[mt][nt][half * 2 + 1] *= inv;
            }
        }
    }
    // P fragments (C-frag -> A-frag identity), then PV
    float ov[2][4][4];
#pragma unroll
    for (int mt = 0; mt < 2; mt++)
#pragma unroll
        for (int nt = 0; nt < 4; nt++)
#pragma unroll
            for (int q = 0; q < 4; q++) ov[mt][nt][q] = 0.f;

#pragma unroll
    for (int ks = 0; ks < 2; ks++) {
        uint32_t vb[2][4];
#pragma unroll
        for (int ntp = 0; ntp < 2; ntp++) {
            int j = ks * 16 + (sel & 1) * 8 + rr;
            int ntile = ntp * 2 + (sel >> 1);
            LDSM_X4_T(vb[ntp], sQ + (uint32_t)(j * SQROWB + 256 + h * 64 + ntile * 16));
        }
#pragma unroll
        for (int mt = 0; mt < 2; mt++) {
            uint32_t pa[4];
            pa[0] = packbf(sc[mt][2 * ks][0], sc[mt][2 * ks][1]);
            pa[1] = packbf(sc[mt][2 * ks][2], sc[mt][2 * ks][3]);
            pa[2] = packbf(sc[mt][2 * ks + 1][0], sc[mt][2 * ks + 1][1]);
            pa[3] = packbf(sc[mt][2 * ks + 1][2], sc[mt][2 * ks + 1][3]);
#pragma unroll
            for (int ntp = 0; ntp < 2; ntp++) {
                mma_bf16(ov[mt][ntp * 2],     pa, vb[ntp][0], vb[ntp][1]);
                mma_bf16(ov[mt][ntp * 2 + 1], pa, vb[ntp][2], vb[ntp][3]);
            }
        }
    }
    // residual + relu + store (rows < 26)
    __nv_bfloat16* outb = Aout + (b0 + s) * ATTFLAT + h * DHEAD;
#pragma unroll
    for (int mt = 0; mt < 2; mt++) {
#pragma unroll
        for (int nt = 0; nt < 4; nt++) {
            int col = nt * 8 + 2 * t4;
            int r0 = mt * 16 + g;
            {
                uint32_t ru = *(const uint32_t*)(sm + OFF_Q + (s * 26 + r0) * SQROWB + 768 + h * 128 + col * 2);
                float2 rf = __bfloat1622float2(*(__nv_bfloat162*)&ru);
                float o0 = fmaxf(ov[mt][nt][0] + rf.x, 0.f);
                float o1 = fmaxf(ov[mt][nt][1] + rf.y, 0.f);
                *(uint32_t*)(outb + (size_t)r0 * EDIM + col) = packbf(o0, o1);
            }
            int r1 = r0 + 8;
            if (mt == 0 || g < 2) {
                uint32_t ru = *(const uint32_t*)(sm + OFF_Q + (s * 26 + r1) * SQROWB + 768 + h * 128 + col * 2);
                float2 rf = __bfloat1622float2(*(__nv_bfloat162*)&ru);
                float o0 = fmaxf(ov[mt][nt][2] + rf.x, 0.f);
                float o1 = fmaxf(ov[mt][nt][3] + rf.y, 0.f);
                *(uint32_t*)(outb + (size_t)r1 * EDIM + col) = packbf(o0, o1);
            }
        }
    }
}

// ---------------- bf16 mma.sync GEMM (dnn layers) ----------------
template<int KTOT, int NTFULL, bool RELU, bool BF16OUT>
__global__ __launch_bounds__(256)
void gemm_mma(const __nv_bfloat16* __restrict__ A,
              const __nv_bfloat16* __restrict__ Bop,
              const float* __restrict__ bias,
              void* __restrict__ Cout) {
    __shared__ __align__(1024) unsigned char smA[128 * 128];
    __shared__ __align__(1024) unsigned char smB[128 * 128];
    const int tid = threadIdx.x;
    const int wid = tid >> 5, lane = tid & 31;
    const int wm = wid & 3, wn = wid >> 2;
    const long m0 = (long)blockIdx.x * 128;
    const int n0 = blockIdx.y * 128;

    float acc[2][8][4];
#pragma unroll
    for (int mi = 0; mi < 2; mi++)
#pragma unroll
        for (int ni = 0; ni < 8; ni++)
#pragma unroll
            for (int q = 0; q < 4; q++) acc[mi][ni][q] = 0.f;

    const uint32_t sA = smem_u32(smA), sB = smem_u32(smB);
    const int sel = lane >> 3, rr = lane & 7;
    const int arow0 = wm * 32 + (sel & 1) * 8 + rr;
    const int ahi = sel >> 1;
    const int brow0 = wn * 64 + (sel >> 1) * 8 + rr;
    const int bhi = sel & 1;

    const int NCH = KTOT / 64;
    for (int ch = 0; ch < NCH; ch++) {
        const unsigned char* Ag = (const unsigned char*)A + (m0 * KTOT + (long)ch * 64) * 2;
        const unsigned char* Bg = (const unsigned char*)Bop + (((long)n0 * KTOT) + (long)ch * 64) * 2;
#pragma unroll 2
        for (int u = tid; u < 1024; u += 256) {
            int r = u >> 3, ck = u & 7;
            uint32_t so = (uint32_t)(r * 128 + ((ck ^ (r & 7)) << 4));
            *(uint4*)(smA + so) = *(const uint4*)(Ag + (long)r * (KTOT * 2) + ck * 16);
            *(uint4*)(smB + so) = *(const uint4*)(Bg + (long)r * (KTOT * 2) + ck * 16);
        }
        __syncthreads();
#pragma unroll
        for (int kk = 0; kk < 4; kk++) {
            uint32_t a[2][4];
#pragma unroll
            for (int mi = 0; mi < 2; mi++) {
                int r = arow0 + mi * 16;
                LDSM_X4(a[mi], sA + r * 128 + ((uint32_t)((2 * kk + ahi) ^ (r & 7)) << 4));
            }
#pragma unroll
            for (int nip = 0; nip < 4; nip++) {
                int r = brow0 + nip * 16;
                uint32_t b[4];
                LDSM_X4(b, sB + r * 128 + ((uint32_t)((2 * kk + bhi) ^ (r & 7)) << 4));
#pragma unroll
                for (int mi = 0; mi < 2; mi++) {
                    mma_bf16(acc[mi][nip * 2],     a[mi], b[0], b[1]);
                    mma_bf16(acc[mi][nip * 2 + 1], a[mi], b[2], b[3]);
                }
            }
        }
        __syncthreads();
    }

    const int g = lane >> 2, t = lane & 3;
#pragma unroll
    for (int mi = 0; mi < 2; mi++) {
#pragma unroll
        for (int ni = 0; ni < 8; ni++) {
            int col = n0 + wn * 64 + ni * 8 + 2 * t;
            long r0 = m0 + wm * 32 + mi * 16 + g;
            float c0 = acc[mi][ni][0], c1 = acc[mi][ni][1];
            float c2 = acc[mi][ni][2], c3 = acc[mi][ni][3];
            if (bias != nullptr) {
                float bb0 = bias[col], bb1 = bias[col + 1];
                c0 += bb0; c1 += bb1; c2 += bb0; c3 += bb1;
            }
            if (RELU) {
                c0 = fmaxf(c0, 0.f); c1 = fmaxf(c1, 0.f);
                c2 = fmaxf(c2, 0.f); c3 = fmaxf(c3, 0.f);
            }
            if (BF16OUT) {
                __nv_bfloat16* base = (__nv_bfloat16*)Cout;
                *(uint32_t*)(base + r0 * NTFULL + col)       = packbf(c0, c1);
                *(uint32_t*)(base + (r0 + 8) * NTFULL + col) = packbf(c2, c3);
            } else {
                float* base = (float*)Cout;
                *(float2*)(base + r0 * NTFULL + col)       = make_float2(c0, c1);
                *(float2*)(base + (r0 + 8) * NTFULL + col) = make_float2(c2, c3);
            }
        }
    }
}

// ---------------- head ----------------
__global__ __launch_bounds__(256)
void head_kernel(const float* __restrict__ X,
                 const __nv_bfloat16* __restrict__ att,
                 const float* __restrict__ outW,
                 const float* __restrict__ linW, const float* __restrict__ linb,
                 float* __restrict__ out) {
    __shared__ __align__(16) float soW[STACKW];
    int tid = threadIdx.x;
    for (int i = tid; i < STACKW; i += 256) soW[i] = outW[i];
    __syncthreads();
    int warp = tid >> 5, lane = tid & 31;
    int s = blockIdx.x * 8 + warp;
    const uint4* ap = (const uint4*)(att + (size_t)s * ATTFLAT);
    float acc = 0.f;
#pragma unroll
    for (int t = 0; t < 7; t++) {
        int i = t * 32 + lane;
        if (t < 6 || lane < 16) {
            uint4 u = ap[i];
            const __nv_bfloat162* hb = (const __nv_bfloat162*)&u;
            const float* w = &soW[i * 8];
#pragma unroll
            for (int q = 0; q < 4; q++) {
                float2 f2 = __bfloat1622float2(hb[q]);
                acc += f2.x * w[2 * q] + f2.y * w[2 * q + 1];
            }
        }
    }
    {
        const float4* hp = (const float4*)&g_h2[(size_t)s * H2DIM];
        float4 a = hp[lane];
        const float4* ow4 = (const float4*)soW;
        float4 w = ow4[ATTFLAT / 4 + lane];
        acc += a.x * w.x + a.y * w.y + a.z * w.z + a.w * w.w;
    }
    float al = X[(size_t)s * XCOLS + lane] * linW[lane];
    if (lane < XCOLS - 32) al += X[(size_t)s * XCOLS + 32 + lane] * linW[32 + lane];
#pragma unroll
    for (int o = 16; o > 0; o >>= 1) {
        acc += __shfl_xor_sync(0xffffffffu, acc, o);
        al  += __shfl_xor_sync(0xffffffffu, al, o);
    }
    if (lane == 0) {
        float lin = fmaxf(al + linb[0], 0.f);
        out[s] = 1.f / (1.f + expf(-(lin + acc)));
    }
}

// ---------------- launcher ----------------
extern "C" void kernel_launch(void* const* d_in, const int* in_sizes, int n_in,
                              void* d_out, int out_size) {
    (void)in_sizes; (void)n_in; (void)out_size;
    const float* X    = (const float*)d_in[0];
    const int*   sidx = (const int*)  d_in[1];
    const float* emb  = (const float*)d_in[2];
    const float* Wq   = (const float*)d_in[3];
    const float* Wk   = (const float*)d_in[4];
    const float* Wv   = (const float*)d_in[5];
    const float* Wr   = (const float*)d_in[6];
    const float* W1   = (const float*)d_in[7];
    const float* b1   = (const float*)d_in[8];
    const float* W2   = (const float*)d_in[9];
    const float* b2   = (const float*)d_in[10];
    const float* outW = (const float*)d_in[11];
    const float* linW = (const float*)d_in[12];
    const float* linb = (const float*)d_in[13];
    float* out = (float*)d_out;

    void *pAttA, *pAttB, *pDnn, *pH1, *pH2, *pWqkvr, *pW1b, *pW2b;
    cudaGetSymbolAddress(&pAttA,  g_attA);
    cudaGetSymbolAddress(&pAttB,  g_attB);
    cudaGetSymbolAddress(&pDnn,   g_dnn_bf);
    cudaGetSymbolAddress(&pH1,    g_h1_bf);
    cudaGetSymbolAddress(&pH2,    g_h2);
    cudaGetSymbolAddress(&pWqkvr, g_wqkvr_bf);
    cudaGetSymbolAddress(&pW1b,   g_w1_bf);
    cudaGetSymbolAddress(&pW2b,   g_w2_bf);

    cudaFuncSetAttribute((const void*)fused_layer,
                         cudaFuncAttributeMaxDynamicSharedMemorySize, F_SMEM);

    prep_all<<<PREP_TOTAL / 256, 256>>>(Wq, Wk, Wv, Wr, W1, W2);
    gather_emb<<<MROWS / 32, 256>>>(sidx, emb);
    dense_pad<<<BATCH * 64 / 256, 256>>>(X);

    const __nv_bfloat16* wbase = (const __nv_bfloat16*)pWqkvr;
    fused_layer<<<BATCH / F_SPB, 256, F_SMEM>>>(
        (const __nv_bfloat16*)pDnn, (long)KPAD, wbase, (__nv_bfloat16*)pAttA);
    fused_layer<<<BATCH / F_SPB, 256, F_SMEM>>>(
        (const __nv_bfloat16*)pAttA, (long)ATTFLAT, wbase + (size_t)QKVR_C * EDIM,
        (__nv_bfloat16*)pAttB);
    fused_layer<<<BATCH / F_SPB, 256, F_SMEM>>>(
        (const __nv_bfloat16*)pAttB, (long)ATTFLAT, wbase + (size_t)2 * QKVR_C * EDIM,
        (__nv_bfloat16*)pAttA);

    gemm_mma<KPAD, H1DIM, true, true><<<dim3(BATCH / 128, H1DIM / 128), 256>>>(
        (const __nv_bfloat16*)pDnn, (const __nv_bfloat16*)pW1b, b1, pH1);
    gemm_mma<H1DIM, H2DIM, true, false><<<dim3(BATCH / 128, 1), 256>>>(
        (const __nv_bfloat16*)pH1, (const __nv_bfloat16*)pW2b, b2, pH2);
    head_kernel<<<BATCH / 8, 256>>>(X, (const __nv_bfloat16*)pAttA, outW, linW, linb, out);
}

// round 12
// speedup vs baseline: 4.7676x; 1.0350x over previous
#include <cuda_runtime.h>
#include <cuda_bf16.h>
#include <cstdint>
#include <math.h>

// ---------------- problem constants ----------------
#define BATCH     32768
#define NSPARSE   26
#define NDENSE    13
#define VOCAB     10000
#define EDIM      64
#define NHEAD     2
#define DHEAD     32
#define NLAYER    3
#define H1DIM     256
#define H2DIM     128
#define DNNIN     1677
#define KPAD      1728            // 27*64 ; dnn cols: [emb 0..1663 | dense | pad]
#define XCOLS     39
#define ATTFLAT   (NSPARSE*EDIM)  // 1664
#define QKVR_C    256
#define MROWS     (BATCH*NSPARSE)
#define STACKW    (ATTFLAT + H2DIM)

// ---------------- scratch ----------------
__device__ __nv_bfloat16  g_attA[(size_t)BATCH * ATTFLAT];
__device__ __nv_bfloat16  g_attB[(size_t)BATCH * ATTFLAT];
__device__ __nv_bfloat16  g_dnn_bf[(size_t)BATCH * KPAD];
__device__ __nv_bfloat16  g_h1_bf[(size_t)BATCH * H1DIM];
__device__ float          g_h2[(size_t)BATCH * H2DIM];
__device__ __nv_bfloat16  g_wqkvr_bf[NLAYER * QKVR_C * EDIM];  // [l][n][k]
__device__ __nv_bfloat16  g_w1_bf[H1DIM * KPAD];
__device__ __nv_bfloat16  g_w2_bf[H2DIM * H1DIM];

// ---------------- mma.sync helpers ----------------
__device__ __forceinline__ uint32_t smem_u32(const void* p) {
    uint32_t a;
    asm("{ .reg .u64 t; cvta.to.shared.u64 t, %1; cvt.u32.u64 %0, t; }" : "=r"(a) : "l"(p));
    return a;
}
#define LDSM_X4(d, addr) \
    asm volatile("ldmatrix.sync.aligned.m8n8.x4.shared.b16 {%0,%1,%2,%3}, [%4];" \
        : "=r"((d)[0]), "=r"((d)[1]), "=r"((d)[2]), "=r"((d)[3]) : "r"(addr))
#define LDSM_X4_T(d, addr) \
    asm volatile("ldmatrix.sync.aligned.m8n8.x4.trans.shared.b16 {%0,%1,%2,%3}, [%4];" \
        : "=r"((d)[0]), "=r"((d)[1]), "=r"((d)[2]), "=r"((d)[3]) : "r"(addr))

__device__ __forceinline__ void mma_bf16(float* c, const uint32_t* a,
                                         uint32_t b0, uint32_t b1) {
    asm volatile(
        "mma.sync.aligned.m16n8k16.row.col.f32.bf16.bf16.f32 "
        "{%0,%1,%2,%3},{%4,%5,%6,%7},{%8,%9},{%0,%1,%2,%3};"
        : "+f"(c[0]), "+f"(c[1]), "+f"(c[2]), "+f"(c[3])
        : "r"(a[0]), "r"(a[1]), "r"(a[2]), "r"(a[3]), "r"(b0), "r"(b1));
}
__device__ __forceinline__ uint32_t packbf(float a, float b) {
    __nv_bfloat162 h = __floats2bfloat162_rn(a, b);
    return *(uint32_t*)&h;
}

// ---------------- merged weight prep ----------------
#define PREP_W1_OFF  (NLAYER * QKVR_C * EDIM)
#define PREP_W2_OFF  (PREP_W1_OFF + H1DIM * KPAD)
#define PREP_TOTAL   (PREP_W2_OFF + H2DIM * H1DIM)
__global__ __launch_bounds__(256)
void prep_all(const float* __restrict__ Wq, const float* __restrict__ Wk,
              const float* __restrict__ Wv, const float* __restrict__ Wr,
              const float* __restrict__ W1, const float* __restrict__ W2) {
    int idx = blockIdx.x * 256 + threadIdx.x;
    if (idx < PREP_W1_OFF) {
        int l = idx >> 14, rem = idx & 16383;
        int n = rem >> 6, k = rem & 63;
        const float* Ws[4] = {Wq, Wk, Wv, Wr};
        g_wqkvr_bf[idx] = __float2bfloat16_rn(Ws[n >> 6][(l * EDIM + k) * EDIM + (n & 63)]);
    } else if (idx < PREP_W2_OFF) {
        int j = idx - PREP_W1_OFF;
        int n = j / KPAD, k = j % KPAD;
        float v = 0.f;
        if (k < ATTFLAT)               v = W1[(long)(13 + k) * H1DIM + n];
        else if (k < ATTFLAT + NDENSE) v = W1[(long)(k - ATTFLAT) * H1DIM + n];
        g_w1_bf[j] = __float2bfloat16_rn(v);
    } else {
        int j = idx - PREP_W2_OFF;
        int n = j / H1DIM, k = j % H1DIM;
        g_w2_bf[j] = __float2bfloat16_rn(W2[(long)k * H2DIM + n]);
    }
}

// ---------------- embedding gather ----------------
__global__ __launch_bounds__(256)
void gather_emb(const int* __restrict__ sidx, const float* __restrict__ emb) {
    int t = threadIdx.x;
    int row = blockIdx.x * 32 + (t >> 3);
    int qi  = t & 7;
    int b = row / NSPARSE, f = row - b * NSPARSE;
    int vrow = sidx[(long)b * NSPARSE + f];
    const float* src = emb + ((long)f * VOCAB + vrow) * EDIM + qi * 8;
    float4 a0 = *(const float4*)src;
    float4 a1 = *(const float4*)(src + 4);
    uint4 o;
    o.x = packbf(a0.x, a0.y); o.y = packbf(a0.z, a0.w);
    o.z = packbf(a1.x, a1.y); o.w = packbf(a1.z, a1.w);
    *(uint4*)(g_dnn_bf + (long)b * KPAD + f * EDIM + qi * 8) = o;
}
__global__ __launch_bounds__(256)
void dense_pad(const float* __restrict__ X) {
    long idx = (long)blockIdx.x * 256 + threadIdx.x;
    int b = (int)(idx >> 6), cc = (int)(idx & 63);
    float v = (cc < NDENSE) ? X[(long)b * XCOLS + NSPARSE + cc] : 0.f;
    g_dnn_bf[(long)b * KPAD + ATTFLAT + cc] = __float2bfloat16_rn(v);
}

// ---------------- fused proj + attention layer (tensor-core attention) ----
// 256 threads, 4 samples/CTA. Warp w: mma for qkvr cols [32w,32w+32) with
// W fragments loaded straight from gmem (no W smem tile), then attention
// task (s=w>>1, h=w&1) on mma.sync. smem 73.5 KB -> 3 CTAs/SM.
#define F_SPB   4
#define SQROWB  528
#define OFF_A   0
#define OFF_Q   (112 * 128)                    // 14336
#define F_SMEM  (OFF_Q + 112 * SQROWB)         // 73472

__global__ __launch_bounds__(256, 3)
void fused_layer(const __nv_bfloat16* __restrict__ Ain, long sstride,
                 const __nv_bfloat16* __restrict__ W,
                 __nv_bfloat16* __restrict__ Aout) {
    extern __shared__ __align__(1024) unsigned char sm[];
    const int tid = threadIdx.x, wid = tid >> 5, lane = tid & 31;
    const long b0 = (long)blockIdx.x * F_SPB;

    // A tile: 112 rows x 128 B (rows 104..111 zero), swizzled
#pragma unroll 4
    for (int u = tid; u < 896; u += 256) {
        int r = u >> 3, ck = u & 7;
        uint4 v = make_uint4(0u, 0u, 0u, 0u);
        if (r < 104) {
            int s = r / 26, f = r - s * 26;
            v = *(const uint4*)((const unsigned char*)(Ain + (b0 + s) * sstride + f * EDIM) + ck * 16);
        }
        *(uint4*)(sm + OFF_A + r * 128 + ((ck ^ (r & 7)) << 4)) = v;
    }

    // W fragments direct from gmem: wf[kk][nt][0..1] for this warp's 32 cols.
    // mma B-frag (row.col): lane l holds W[(n0 + l/4)*64 + k0 + (l%4)*2 .. +1]
    uint32_t wf[4][4][2];
    {
        const __nv_bfloat16* Wl = W + (lane >> 2) * 64 + (lane & 3) * 2;
#pragma unroll
        for (int nt = 0; nt < 4; nt++) {
            const __nv_bfloat16* Wn = Wl + (wid * 32 + nt * 8) * 64;
#pragma unroll
            for (int kk = 0; kk < 4; kk++) {
                wf[kk][nt][0] = *(const uint32_t*)(Wn + kk * 16);
                wf[kk][nt][1] = *(const uint32_t*)(Wn + kk * 16 + 8);
            }
        }
    }
    __syncthreads();

    const uint32_t sA = smem_u32(sm + OFF_A);
    const int sel = lane >> 3, rr = lane & 7;
    const int g = lane >> 2, t4 = lane & 3;

    // 7 m-tiles of 16 rows
    for (int mt = 0; mt < 7; mt++) {
        float acc[4][4];
#pragma unroll
        for (int ni = 0; ni < 4; ni++)
#pragma unroll
            for (int q = 0; q < 4; q++) acc[ni][q] = 0.f;
#pragma unroll
        for (int kk = 0; kk < 4; kk++) {
            uint32_t a[4];
            int ra = mt * 16 + (sel & 1) * 8 + rr;
            LDSM_X4(a, sA + ra * 128 + ((uint32_t)((2 * kk + (sel >> 1)) ^ (ra & 7)) << 4));
#pragma unroll
            for (int nt = 0; nt < 4; nt++)
                mma_bf16(acc[nt], a, wf[kk][nt][0], wf[kk][nt][1]);
        }
#pragma unroll
        for (int ni = 0; ni < 4; ni++) {
            int col = wid * 32 + ni * 8 + 2 * t4;
            int r0 = mt * 16 + g;
            *(uint32_t*)(sm + OFF_Q + (long)r0 * SQROWB + col * 2) = packbf(acc[ni][0], acc[ni][1]);
            *(uint32_t*)(sm + OFF_Q + (long)(r0 + 8) * SQROWB + col * 2) = packbf(acc[ni][2], acc[ni][3]);
        }
    }
    __syncthreads();

    // ---------- attention on tensor cores: warp -> (s = w>>1, h = w&1) ----
    const int s = wid >> 1, h = wid & 1;
    const uint32_t sQ = smem_u32(sm + OFF_Q) + (uint32_t)(s * 26 * SQROWB);

    // scores S[32,32]
    float sc[2][4][4];
#pragma unroll
    for (int mt = 0; mt < 2; mt++)
#pragma unroll
        for (int nt = 0; nt < 4; nt++)
#pragma unroll
            for (int q = 0; q < 4; q++) sc[mt][nt][q] = 0.f;

#pragma unroll
    for (int ks = 0; ks < 2; ks++) {
        uint32_t qf[2][4];
#pragma unroll
        for (int mt = 0; mt < 2; mt++) {
            int r = mt * 16 + (sel & 1) * 8 + rr;
            LDSM_X4(qf[mt], sQ + (uint32_t)(r * SQROWB + h * 64 + ks * 32 + (sel >> 1) * 16));
        }
#pragma unroll
        for (int ntp = 0; ntp < 2; ntp++) {
            int jn = ntp * 16 + (sel >> 1) * 8 + rr;
            uint32_t kf[4];
            LDSM_X4(kf, sQ + (uint32_t)(jn * SQROWB + 128 + h * 64 + ks * 32 + (sel & 1) * 16));
#pragma unroll
            for (int mt = 0; mt < 2; mt++) {
                mma_bf16(sc[mt][ntp * 2],     qf[mt], kf[0], kf[1]);
                mma_bf16(sc[mt][ntp * 2 + 1], qf[mt], kf[2], kf[3]);
            }
        }
    }
    // mask cols >= 26
#pragma unroll
    for (int mt = 0; mt < 2; mt++)
#pragma unroll
        for (int q = 0; q < 4; q++) {
            int col = 24 + 2 * t4 + (q & 1);
            if (col >= 26) sc[mt][3][q] = -INFINITY;
        }
    // softmax per row; in-lane then quad shuffles
#pragma unroll
    for (int mt = 0; mt < 2; mt++) {
#pragma unroll
        for (int half = 0; half < 2; half++) {
            float m = -INFINITY;
#pragma unroll
            for (int nt = 0; nt < 4; nt++)
                m = fmaxf(m, fmaxf(sc[mt][nt][half * 2], sc[mt][nt][half * 2 + 1]));
            m = fmaxf(m, __shfl_xor_sync(0xffffffffu, m, 1));
            m = fmaxf(m, __shfl_xor_sync(0xffffffffu, m, 2));
            float ssum = 0.f;
#pragma unroll
            for (int nt = 0; nt < 4; nt++) {
                float e0 = __expf(sc[mt][nt][half * 2] - m);
                float e1 = __expf(sc[mt][nt][half * 2 + 1] - m);
                sc[mt][nt][half * 2] = e0; sc[mt][nt][half * 2 + 1] = e1;
                ssum += e0 + e1;
            }
            ssum += __shfl_xor_sync(0xffffffffu, ssum, 1);
            ssum += __shfl_xor_sync(0xffffffffu, ssum, 2);
            float inv = 1.f / ssum;
#pragma unroll
            for (int nt = 0; nt < 4; nt++) {
                sc[mt][nt][half * 2] *= inv;
                sc[mt][nt][half * 2 + 1] *= inv;
            }
        }
    }
    // P fragments -> PV
    float ov[2][4][4];
#pragma unroll
    for (int mt = 0; mt < 2; mt++)
#pragma unroll
        for (int nt = 0; nt < 4; nt++)
#pragma unroll
            for (int q = 0; q < 4; q++) ov[mt][nt][q] = 0.f;

#pragma unroll
    for (int ks = 0; ks < 2; ks++) {
        uint32_t vb[2][4];
#pragma unroll
        for (int ntp = 0; ntp < 2; ntp++) {
            int j = ks * 16 + (sel & 1) * 8 + rr;
            int ntile = ntp * 2 + (sel >> 1);
            LDSM_X4_T(vb[ntp], sQ + (uint32_t)(j * SQROWB + 256 + h * 64 + ntile * 16));
        }
#pragma unroll
        for (int mt = 0; mt < 2; mt++) {
            uint32_t pa[4];
            pa[0] = packbf(sc[mt][2 * ks][0], sc[mt][2 * ks][1]);
            pa[1] = packbf(sc[mt][2 * ks][2], sc[mt][2 * ks][3]);
            pa[2] = packbf(sc[mt][2 * ks + 1][0], sc[mt][2 * ks + 1][1]);
            pa[3] = packbf(sc[mt][2 * ks + 1][2], sc[mt][2 * ks + 1][3]);
#pragma unroll
            for (int ntp = 0; ntp < 2; ntp++) {
                mma_bf16(ov[mt][ntp * 2],     pa, vb[ntp][0], vb[ntp][1]);
                mma_bf16(ov[mt][ntp * 2 + 1], pa, vb[ntp][2], vb[ntp][3]);
            }
        }
    }
    // residual (res = cols 192 + h*32 -> bytes 384 + h*64) + relu + store
    __nv_bfloat16* outb = Aout + (b0 + s) * ATTFLAT + h * DHEAD;
#pragma unroll
    for (int mt = 0; mt < 2; mt++) {
#pragma unroll
        for (int nt = 0; nt < 4; nt++) {
            int col = nt * 8 + 2 * t4;
            int r0 = mt * 16 + g;
            {
                uint32_t ru = *(const uint32_t*)(sm + OFF_Q + (s * 26 + r0) * SQROWB + 384 + h * 64 + col * 2);
                float2 rf = __bfloat1622float2(*(__nv_bfloat162*)&ru);
                float o0 = fmaxf(ov[mt][nt][0] + rf.x, 0.f);
                float o1 = fmaxf(ov[mt][nt][1] + rf.y, 0.f);
                *(uint32_t*)(outb + (size_t)r0 * EDIM + col) = packbf(o0, o1);
            }
            int r1 = r0 + 8;
            if (mt == 0 || g < 2) {
                uint32_t ru = *(const uint32_t*)(sm + OFF_Q + (s * 26 + r1) * SQROWB + 384 + h * 64 + col * 2);
                float2 rf = __bfloat1622float2(*(__nv_bfloat162*)&ru);
                float o0 = fmaxf(ov[mt][nt][2] + rf.x, 0.f);
                float o1 = fmaxf(ov[mt][nt][3] + rf.y, 0.f);
                *(uint32_t*)(outb + (size_t)r1 * EDIM + col) = packbf(o0, o1);
            }
        }
    }
}

// ---------------- bf16 mma.sync GEMM (dnn layers) ----------------
template<int KTOT, int NTFULL, bool RELU, bool BF16OUT>
__global__ __launch_bounds__(256)
void gemm_mma(const __nv_bfloat16* __restrict__ A,
              const __nv_bfloat16* __restrict__ Bop,
              const float* __restrict__ bias,
              void* __restrict__ Cout) {
    __shared__ __align__(1024) unsigned char smA[128 * 128];
    __shared__ __align__(1024) unsigned char smB[128 * 128];
    const int tid = threadIdx.x;
    const int wid = tid >> 5, lane = tid & 31;
    const int wm = wid & 3, wn = wid >> 2;
    const long m0 = (long)blockIdx.x * 128;
    const int n0 = blockIdx.y * 128;

    float acc[2][8][4];
#pragma unroll
    for (int mi = 0; mi < 2; mi++)
#pragma unroll
        for (int ni = 0; ni < 8; ni++)
#pragma unroll
            for (int q = 0; q < 4; q++) acc[mi][ni][q] = 0.f;

    const uint32_t sA = smem_u32(smA), sB = smem_u32(smB);
    const int sel = lane >> 3, rr = lane & 7;
    const int arow0 = wm * 32 + (sel & 1) * 8 + rr;
    const int ahi = sel >> 1;
    const int brow0 = wn * 64 + (sel >> 1) * 8 + rr;
    const int bhi = sel & 1;

    const int NCH = KTOT / 64;
    for (int ch = 0; ch < NCH; ch++) {
        const unsigned char* Ag = (const unsigned char*)A + (m0 * KTOT + (long)ch * 64) * 2;
        const unsigned char* Bg = (const unsigned char*)Bop + (((long)n0 * KTOT) + (long)ch * 64) * 2;
#pragma unroll 2
        for (int u = tid; u < 1024; u += 256) {
            int r = u >> 3, ck = u & 7;
            uint32_t so = (uint32_t)(r * 128 + ((ck ^ (r & 7)) << 4));
            *(uint4*)(smA + so) = *(const uint4*)(Ag + (long)r * (KTOT * 2) + ck * 16);
            *(uint4*)(smB + so) = *(const uint4*)(Bg + (long)r * (KTOT * 2) + ck * 16);
        }
        __syncthreads();
#pragma unroll
        for (int kk = 0; kk < 4; kk++) {
            uint32_t a[2][4];
#pragma unroll
            for (int mi = 0; mi < 2; mi++) {
                int r = arow0 + mi * 16;
                LDSM_X4(a[mi], sA + r * 128 + ((uint32_t)((2 * kk + ahi) ^ (r & 7)) << 4));
            }
#pragma unroll
            for (int nip = 0; nip < 4; nip++) {
                int r = brow0 + nip * 16;
                uint32_t b[4];
                LDSM_X4(b, sB + r * 128 + ((uint32_t)((2 * kk + bhi) ^ (r & 7)) << 4));
#pragma unroll
                for (int mi = 0; mi < 2; mi++) {
                    mma_bf16(acc[mi][nip * 2],     a[mi], b[0], b[1]);
                    mma_bf16(acc[mi][nip * 2 + 1], a[mi], b[2], b[3]);
                }
            }
        }
        __syncthreads();
    }

    const int g = lane >> 2, t = lane & 3;
#pragma unroll
    for (int mi = 0; mi < 2; mi++) {
#pragma unroll
        for (int ni = 0; ni < 8; ni++) {
            int col = n0 + wn * 64 + ni * 8 + 2 * t;
            long r0 = m0 + wm * 32 + mi * 16 + g;
            float c0 = acc[mi][ni][0], c1 = acc[mi][ni][1];
            float c2 = acc[mi][ni][2], c3 = acc[mi][ni][3];
            if (bias != nullptr) {
                float bb0 = bias[col], bb1 = bias[col + 1];
                c0 += bb0; c1 += bb1; c2 += bb0; c3 += bb1;
            }
            if (RELU) {
                c0 = fmaxf(c0, 0.f); c1 = fmaxf(c1, 0.f);
                c2 = fmaxf(c2, 0.f); c3 = fmaxf(c3, 0.f);
            }
            if (BF16OUT) {
                __nv_bfloat16* base = (__nv_bfloat16*)Cout;
                *(uint32_t*)(base + r0 * NTFULL + col)       = packbf(c0, c1);
                *(uint32_t*)(base + (r0 + 8) * NTFULL + col) = packbf(c2, c3);
            } else {
                float* base = (float*)Cout;
                *(float2*)(base + r0 * NTFULL + col)       = make_float2(c0, c1);
                *(float2*)(base + (r0 + 8) * NTFULL + col) = make_float2(c2, c3);
            }
        }
    }
}

// ---------------- head ----------------
__global__ __launch_bounds__(256)
void head_kernel(const float* __restrict__ X,
                 const __nv_bfloat16* __restrict__ att,
                 const float* __restrict__ outW,
                 const float* __restrict__ linW, const float* __restrict__ linb,
                 float* __restrict__ out) {
    __shared__ __align__(16) float soW[STACKW];
    int tid = threadIdx.x;
    for (int i = tid; i < STACKW; i += 256) soW[i] = outW[i];
    __syncthreads();
    int warp = tid >> 5, lane = tid & 31;
    int s = blockIdx.x * 8 + warp;
    const uint4* ap = (const uint4*)(att + (size_t)s * ATTFLAT);
    float acc = 0.f;
#pragma unroll
    for (int t = 0; t < 7; t++) {
        int i = t * 32 + lane;
        if (t < 6 || lane < 16) {
            uint4 u = ap[i];
            const __nv_bfloat162* hb = (const __nv_bfloat162*)&u;
            const float* w = &soW[i * 8];
#pragma unroll
            for (int q = 0; q < 4; q++) {
                float2 f2 = __bfloat1622float2(hb[q]);
                acc += f2.x * w[2 * q] + f2.y * w[2 * q + 1];
            }
        }
    }
    {
        const float4* hp = (const float4*)&g_h2[(size_t)s * H2DIM];
        float4 a = hp[lane];
        const float4* ow4 = (const float4*)soW;
        float4 w = ow4[ATTFLAT / 4 + lane];
        acc += a.x * w.x + a.y * w.y + a.z * w.z + a.w * w.w;
    }
    float al = X[(size_t)s * XCOLS + lane] * linW[lane];
    if (lane < XCOLS - 32) al += X[(size_t)s * XCOLS + 32 + lane] * linW[32 + lane];
#pragma unroll
    for (int o = 16; o > 0; o >>= 1) {
        acc += __shfl_xor_sync(0xffffffffu, acc, o);
        al  += __shfl_xor_sync(0xffffffffu, al, o);
    }
    if (lane == 0) {
        float lin = fmaxf(al + linb[0], 0.f);
        out[s] = 1.f / (1.f + expf(-(lin + acc)));
    }
}

// ---------------- launcher ----------------
extern "C" void kernel_launch(void* const* d_in, const int* in_sizes, int n_in,
                              void* d_out, int out_size) {
    (void)in_sizes; (void)n_in; (void)out_size;
    const float* X    = (const float*)d_in[0];
    const int*   sidx = (const int*)  d_in[1];
    const float* emb  = (const float*)d_in[2];
    const float* Wq   = (const float*)d_in[3];
    const float* Wk   = (const float*)d_in[4];
    const float* Wv   = (const float*)d_in[5];
    const float* Wr   = (const float*)d_in[6];
    const float* W1   = (const float*)d_in[7];
    const float* b1   = (const float*)d_in[8];
    const float* W2   = (const float*)d_in[9];
    const float* b2   = (const float*)d_in[10];
    const float* outW = (const float*)d_in[11];
    const float* linW = (const float*)d_in[12];
    const float* linb = (const float*)d_in[13];
    float* out = (float*)d_out;

    void *pAttA, *pAttB, *pDnn, *pH1, *pH2, *pWqkvr, *pW1b, *pW2b;
    cudaGetSymbolAddress(&pAttA,  g_attA);
    cudaGetSymbolAddress(&pAttB,  g_attB);
    cudaGetSymbolAddress(&pDnn,   g_dnn_bf);
    cudaGetSymbolAddress(&pH1,    g_h1_bf);
    cudaGetSymbolAddress(&pH2,    g_h2);
    cudaGetSymbolAddress(&pWqkvr, g_wqkvr_bf);
    cudaGetSymbolAddress(&pW1b,   g_w1_bf);
    cudaGetSymbolAddress(&pW2b,   g_w2_bf);

    cudaFuncSetAttribute((const void*)fused_layer,
                         cudaFuncAttributeMaxDynamicSharedMemorySize, F_SMEM);

    prep_all<<<PREP_TOTAL / 256, 256>>>(Wq, Wk, Wv, Wr, W1, W2);
    gather_emb<<<MROWS / 32, 256>>>(sidx, emb);
    dense_pad<<<BATCH * 64 / 256, 256>>>(X);

    const __nv_bfloat16* wbase = (const __nv_bfloat16*)pWqkvr;
    fused_layer<<<BATCH / F_SPB, 256, F_SMEM>>>(
        (const __nv_bfloat16*)pDnn, (long)KPAD, wbase, (__nv_bfloat16*)pAttA);
    fused_layer<<<BATCH / F_SPB, 256, F_SMEM>>>(
        (const __nv_bfloat16*)pAttA, (long)ATTFLAT, wbase + (size_t)QKVR_C * EDIM,
        (__nv_bfloat16*)pAttB);
    fused_layer<<<BATCH / F_SPB, 256, F_SMEM>>>(
        (const __nv_bfloat16*)pAttB, (long)ATTFLAT, wbase + (size_t)2 * QKVR_C * EDIM,
        (__nv_bfloat16*)pAttA);

    gemm_mma<KPAD, H1DIM, true, true><<<dim3(BATCH / 128, H1DIM / 128), 256>>>(
        (const __nv_bfloat16*)pDnn, (const __nv_bfloat16*)pW1b, b1, pH1);
    gemm_mma<H1DIM, H2DIM, true, false><<<dim3(BATCH / 128, 1), 256>>>(
        (const __nv_bfloat16*)pH1, (const __nv_bfloat16*)pW2b, b2, pH2);
    head_kernel<<<BATCH / 8, 256>>>(X, (const __nv_bfloat16*)pAttA, outW, linW, linb, out);
}